// round 11
// baseline (speedup 1.0000x reference)
#include <cuda_runtime.h>
#include <cuda_bf16.h>
#include <math.h>
#include <stdint.h>

#define BB 4096
#define EE 128
#define MMOD 8
#define NSTEPS 3
#define HDIM 256
#define CDIM 16
#define TILE 64
#define NTHR 256
#define MAXT 72

#define S128B 272   // row stride (bytes), K=128 bf16 images
#define S256B 528   // row stride, K=256 images
#define HIMG  33792 // one 64x256 bf16 image (64*528)

// P1 smem: A hi/lo (64x128) + W-half hi/lo (64 rows)
#define P1_AH 0
#define P1_AL 17408
#define P1_WH 34816
#define P1_WL 52224
#define P1_SMEM 69632
// P2 smem: H hi/lo (64x256) + Wf-quarter hi/lo (32 rows)
#define P2_HH 0
#define P2_HL 33792
#define P2_WH 67584
#define P2_WL 84480
#define P2_SMEM 101376
// head P2 smem
#define HP2_HH 0
#define HP2_HL 33792
#define HP2_WH 67584
#define HP2_WL 76032
#define HP2_SMEM 84480

// ---------------- global scratch ------------------------------------------
__device__ uint32_t g_Xpair[2][BB * 64];            // state: packed bf16 hi/lo
__device__ int g_order[NSTEPS * BB];
__device__ int g_tiles[NSTEPS * MAXT * 3];
__device__ __align__(256) uint8_t g_Himg[2][MAXT * HIMG];   // per-tile H images
__device__ __align__(256) uint8_t g_WinT[2][MMOD * 34816];  // [o=128][e=128]
__device__ __align__(256) uint8_t g_WbiT[2][MMOD * 34816];
__device__ __align__(256) uint8_t g_WfT [2][MMOD * 67584];  // [o=128][f=256]
__device__ __align__(256) uint8_t g_W1T [2][69632];         // [j=256][e=128]
__device__ __align__(256) uint8_t g_W2T [2][8448];          // [c=16][j=256]

// ---------------- helpers ---------------------------------------------------
__device__ __forceinline__ uint32_t sptr(const void* p) {
    return (uint32_t)__cvta_generic_to_shared(p);
}
__device__ __forceinline__ void sts32(uint32_t a, uint32_t v) {
    asm volatile("st.shared.b32 [%0], %1;" :: "r"(a), "r"(v) : "memory");
}
__device__ __forceinline__ void cpa16(uint32_t s, const void* g) {
    asm volatile("cp.async.ca.shared.global [%0], [%1], 16;" :: "r"(s), "l"(g));
}
__device__ __forceinline__ void cpa_commit() { asm volatile("cp.async.commit_group;"); }
__device__ __forceinline__ void cpa_wait0()  { asm volatile("cp.async.wait_group 0;"); }
__device__ __forceinline__ void cpa_copy(uint32_t dst, const uint8_t* src, int bytes, int tid) {
    for (int off = tid * 16; off < bytes; off += NTHR * 16) cpa16(dst + off, src + off);
}
__device__ __forceinline__ void splitf(float v0, float v1, uint32_t& h, uint32_t& l) {
    __nv_bfloat16 h0 = __float2bfloat16(v0), h1 = __float2bfloat16(v1);
    float r0 = v0 - __bfloat162float(h0), r1 = v1 - __bfloat162float(h1);
    __nv_bfloat16 l0 = __float2bfloat16(r0), l1 = __float2bfloat16(r1);
    h = (uint32_t)__bfloat16_as_ushort(h0) | ((uint32_t)__bfloat16_as_ushort(h1) << 16);
    l = (uint32_t)__bfloat16_as_ushort(l0) | ((uint32_t)__bfloat16_as_ushort(l1) << 16);
}
__device__ __forceinline__ void ldsm4(uint32_t* a, uint32_t addr) {
    asm volatile("ldmatrix.sync.aligned.m8n8.x4.shared.b16 {%0,%1,%2,%3}, [%4];"
                 : "=r"(a[0]), "=r"(a[1]), "=r"(a[2]), "=r"(a[3]) : "r"(addr));
}
__device__ __forceinline__ void ldsm2(uint32_t& b0, uint32_t& b1, uint32_t addr) {
    asm volatile("ldmatrix.sync.aligned.m8n8.x2.shared.b16 {%0,%1}, [%2];"
                 : "=r"(b0), "=r"(b1) : "r"(addr));
}
__device__ __forceinline__ void mma4(float* c, const uint32_t* a, uint32_t b0, uint32_t b1) {
    asm volatile("mma.sync.aligned.m16n8k16.row.col.f32.bf16.bf16.f32 "
                 "{%0,%1,%2,%3},{%4,%5,%6,%7},{%8,%9},{%0,%1,%2,%3};"
                 : "+f"(c[0]), "+f"(c[1]), "+f"(c[2]), "+f"(c[3])
                 : "r"(a[0]), "r"(a[1]), "r"(a[2]), "r"(a[3]), "r"(b0), "r"(b1));
}

// Fragment-reuse warp GEMM, 3-term hi/lo split (Ah*Bh + Ah*Bl + Al*Bh).
// acc layout: [ms(2)][nt(NT)][4]. M stripes mbase, mbase+16.
template<int NT, int KS, int SBA, int SBB>
__device__ __forceinline__ void wgemm(float* acc,
                                      uint32_t aHI, uint32_t aLO,
                                      uint32_t bHI, uint32_t bLO,
                                      int mbase, int nbase, int lane) {
    const uint32_t aoff = (uint32_t)(mbase + (lane & 15)) * SBA + ((lane >> 4) * 16);
    const uint32_t boff = (uint32_t)(nbase + (lane & 7)) * SBB + (((lane >> 3) & 1) * 16);
    const uint32_t AH = aHI + aoff, AL = aLO + aoff;
    const uint32_t BH = bHI + boff, BL = bLO + boff;
#pragma unroll
    for (int k = 0; k < KS; k++) {
        uint32_t ah0[4], ah1[4], al0[4], al1[4];
        ldsm4(ah0, AH + k * 32);
        ldsm4(ah1, AH + 16 * SBA + k * 32);
        ldsm4(al0, AL + k * 32);
        ldsm4(al1, AL + 16 * SBA + k * 32);
#pragma unroll
        for (int nt = 0; nt < NT; nt++) {
            uint32_t bh0, bh1, bl0, bl1;
            ldsm2(bh0, bh1, BH + nt * 8 * SBB + k * 32);
            ldsm2(bl0, bl1, BL + nt * 8 * SBB + k * 32);
            float* c0 = acc + (0 * NT + nt) * 4;
            float* c1 = acc + (1 * NT + nt) * 4;
            mma4(c0, ah0, bh0, bh1);
            mma4(c1, ah1, bh0, bh1);
            mma4(c0, ah0, bl0, bl1);
            mma4(c1, ah1, bl0, bl1);
            mma4(c0, al0, bh0, bh1);
            mma4(c1, al1, bh0, bh1);
        }
    }
}

// ---------------------------------------------------------------------------
__global__ void setup_kernel(const int* __restrict__ module_ids) {
    __shared__ int cnt[MMOD], cur[MMOD];
    int tid = threadIdx.x, s = blockIdx.x;
    if (tid < MMOD) cnt[tid] = 0;
    __syncthreads();
    for (int b = tid; b < BB; b += NTHR)
        atomicAdd(&cnt[module_ids[b * NSTEPS + s]], 1);
    __syncthreads();
    if (tid == 0) {
        int o = 0, t = 0;
        for (int m = 0; m < MMOD; m++) {
            cur[m] = o;
            int c = cnt[m];
            for (int ch = 0; ch < c; ch += TILE) {
                g_tiles[(s * MAXT + t) * 3 + 0] = m;
                g_tiles[(s * MAXT + t) * 3 + 1] = o + ch;
                g_tiles[(s * MAXT + t) * 3 + 2] = min(TILE, c - ch);
                t++;
            }
            o += c;
        }
        for (; t < MAXT; t++) g_tiles[(s * MAXT + t) * 3 + 2] = 0;
    }
    __syncthreads();
    for (int b = tid; b < BB; b += NTHR) {
        int m = module_ids[b * NSTEPS + s];
        int p = atomicAdd(&cur[m], 1);
        g_order[s * BB + p] = b;
    }
}

__global__ void xform_kernel(const float* __restrict__ W_in,
                             const float* __restrict__ W_bias,
                             const float* __restrict__ W_f,
                             const float* __restrict__ W1,
                             const float* __restrict__ W2) {
    int j = blockIdx.y;
    const float* src; uint8_t *dh, *dl; int R, C, SB;
    if (j < 8)       { src = W_in + j * 16384;  dh = g_WinT[0] + j * 34816; dl = g_WinT[1] + j * 34816; R = 128; C = 128; SB = S128B; }
    else if (j < 16) { int q = j - 8;  src = W_bias + q * 16384; dh = g_WbiT[0] + q * 34816; dl = g_WbiT[1] + q * 34816; R = 128; C = 128; SB = S128B; }
    else if (j < 24) { int q = j - 16; src = W_f + q * 32768;    dh = g_WfT[0] + q * 67584;  dl = g_WfT[1] + q * 67584;  R = 128; C = 256; SB = S256B; }
    else if (j == 24){ src = W1; dh = g_W1T[0]; dl = g_W1T[1]; R = 256; C = 128; SB = S128B; }
    else             { src = W2; dh = g_W2T[0]; dl = g_W2T[1]; R = 16;  C = 256; SB = S256B; }
    int units = R * C / 2;
    for (int u = blockIdx.x * NTHR + threadIdx.x; u < units; u += gridDim.x * NTHR) {
        int rr = u % R, cc = (u / R) * 2;
        float v0 = src[(size_t)cc * R + rr];
        float v1 = src[(size_t)(cc + 1) * R + rr];
        uint32_t h, l;
        splitf(v0, v1, h, l);
        *(uint32_t*)(dh + (size_t)rr * SB + cc * 2) = h;
        *(uint32_t*)(dl + (size_t)rr * SB + cc * 2) = l;
    }
}

// ---------------------------------------------------------------------------
// Step P1: CTA = (tile, half in/bias, N-half). grid 72*2*2=288.
// Computes 64 output cols of Hin or Hbi, writes them into the tile's H image.
// ---------------------------------------------------------------------------
__global__ __launch_bounds__(NTHR)
void step_p1(int s, const float* __restrict__ emb, const int* __restrict__ eids,
             const float* __restrict__ b_in, const float* __restrict__ b_bias) {
    extern __shared__ uint8_t raw[];
    const uint32_t base = sptr(raw);
    __shared__ int srow[TILE];
    __shared__ float sb[TILE];
    int tid = threadIdx.x, wid = tid >> 5, lane = tid & 31;
    int t = blockIdx.x >> 2, h = (blockIdx.x >> 1) & 1, nh = blockIdx.x & 1;

    int m   = g_tiles[(s * MAXT + t) * 3 + 0];
    int bse = g_tiles[(s * MAXT + t) * 3 + 1];
    int cnt = g_tiles[(s * MAXT + t) * 3 + 2];
    if (cnt == 0) return;

    const uint8_t* WH = (h ? g_WbiT[0] : g_WinT[0]) + m * 34816 + nh * 64 * S128B;
    const uint8_t* WL = (h ? g_WbiT[1] : g_WinT[1]) + m * 34816 + nh * 64 * S128B;
    cpa_copy(base + P1_WH, WH, 17408, tid);
    cpa_copy(base + P1_WL, WL, 17408, tid);
    cpa_commit();

    if (tid < TILE) {
        int row = g_order[s * BB + bse + (tid < cnt ? tid : 0)];
        srow[tid] = h ? eids[row * (NSTEPS + 1) + s + 1]
                      : ((s == 0) ? eids[row * (NSTEPS + 1)] : row);
        sb[tid] = h ? b_bias[m * EE + nh * 64 + tid] : b_in[m * EE + nh * 64 + tid];
    }
    __syncthreads();

    const bool frompair = (h == 0 && s > 0);
    for (int i = tid; i < TILE * 64; i += NTHR) {
        int r = i >> 6, k = i & 63;
        uint32_t hh, ll;
        if (frompair) {
            hh = g_Xpair[0][srow[r] * 64 + k];
            ll = g_Xpair[1][srow[r] * 64 + k];
        } else {
            float2 v = *(const float2*)&emb[(size_t)srow[r] * EE + 2 * k];
            splitf(v.x, v.y, hh, ll);
        }
        sts32(base + P1_AH + r * S128B + k * 4, hh);
        sts32(base + P1_AL + r * S128B + k * 4, ll);
    }
    cpa_wait0();
    __syncthreads();

    const int mh = wid >> 2, nq = wid & 3;     // nq*16 cols, NT=2
    const int g = lane >> 2, cp = (lane & 3) * 2;
    float acc[2 * 2 * 4];
#pragma unroll
    for (int i = 0; i < 16; i++) acc[i] = 0.f;
    wgemm<2, 8, S128B, S128B>(acc, base + P1_AH, base + P1_AL,
                              base + P1_WH, base + P1_WL, mh * 32, nq * 16, lane);

    uint8_t* HD0 = g_Himg[0] + t * HIMG + h * 256 + nh * 128;  // byte col offset
    uint8_t* HD1 = g_Himg[1] + t * HIMG + h * 256 + nh * 128;
#pragma unroll
    for (int ms = 0; ms < 2; ms++)
#pragma unroll
        for (int nt = 0; nt < 2; nt++) {
            int r0 = mh * 32 + ms * 16 + g;
            int cl = nq * 16 + nt * 8 + cp;    // local col 0..63
            float* c = acc + (ms * 2 + nt) * 4;
            uint32_t hh, ll;
            splitf(fmaxf(c[0] + sb[cl], 0.f), fmaxf(c[1] + sb[cl + 1], 0.f), hh, ll);
            *(uint32_t*)(HD0 + (size_t)r0 * S256B + cl * 2) = hh;
            *(uint32_t*)(HD1 + (size_t)r0 * S256B + cl * 2) = ll;
            splitf(fmaxf(c[2] + sb[cl], 0.f), fmaxf(c[3] + sb[cl + 1], 0.f), hh, ll);
            *(uint32_t*)(HD0 + (size_t)(r0 + 8) * S256B + cl * 2) = hh;
            *(uint32_t*)(HD1 + (size_t)(r0 + 8) * S256B + cl * 2) = ll;
        }
}

// ---------------------------------------------------------------------------
// Step P2: CTA = (tile, N-quarter). grid 288. 32 out cols per CTA.
// ---------------------------------------------------------------------------
__global__ __launch_bounds__(NTHR)
void step_p2(int s, const float* __restrict__ b_f) {
    extern __shared__ uint8_t raw[];
    const uint32_t base = sptr(raw);
    __shared__ int ridx[TILE];
    __shared__ float sb[32];
    int tid = threadIdx.x, wid = tid >> 5, lane = tid & 31;
    int t = blockIdx.x >> 2, nqt = blockIdx.x & 3;

    int m   = g_tiles[(s * MAXT + t) * 3 + 0];
    int bse = g_tiles[(s * MAXT + t) * 3 + 1];
    int cnt = g_tiles[(s * MAXT + t) * 3 + 2];
    if (cnt == 0) return;

    cpa_copy(base + P2_HH, g_Himg[0] + t * HIMG, HIMG, tid);
    cpa_copy(base + P2_HL, g_Himg[1] + t * HIMG, HIMG, tid);
    cpa_copy(base + P2_WH, g_WfT[0] + m * 67584 + nqt * 32 * S256B, 16896, tid);
    cpa_copy(base + P2_WL, g_WfT[1] + m * 67584 + nqt * 32 * S256B, 16896, tid);
    cpa_commit();

    if (tid < TILE) ridx[tid] = g_order[s * BB + bse + (tid < cnt ? tid : 0)];
    if (tid < 32)   sb[tid] = b_f[m * EE + nqt * 32 + tid];
    cpa_wait0();
    __syncthreads();

    const int mh = wid >> 2, nq = wid & 3;   // nq*8 cols, NT=1
    const int g = lane >> 2, cp = (lane & 3) * 2;
    float acc[2 * 1 * 4];
#pragma unroll
    for (int i = 0; i < 8; i++) acc[i] = 0.f;
    wgemm<1, 16, S256B, S256B>(acc, base + P2_HH, base + P2_HL,
                               base + P2_WH, base + P2_WL, mh * 32, nq * 8, lane);

#pragma unroll
    for (int ms = 0; ms < 2; ms++) {
        int r0 = mh * 32 + ms * 16 + g;
        int cl = nq * 8 + cp;
        int cg = nqt * 32 + cl;
        float* c = acc + ms * 4;
        uint32_t hh, ll;
        if (r0 < cnt) {
            int gr = ridx[r0];
            splitf(tanhf(c[0] + sb[cl]), tanhf(c[1] + sb[cl + 1]), hh, ll);
            g_Xpair[0][gr * 64 + (cg >> 1)] = hh;
            g_Xpair[1][gr * 64 + (cg >> 1)] = ll;
        }
        if (r0 + 8 < cnt) {
            int gr = ridx[r0 + 8];
            splitf(tanhf(c[2] + sb[cl]), tanhf(c[3] + sb[cl + 1]), hh, ll);
            g_Xpair[0][gr * 64 + (cg >> 1)] = hh;
            g_Xpair[1][gr * 64 + (cg >> 1)] = ll;
        }
    }
}

// ---------------------------------------------------------------------------
// Head P1: CTA = (tile, j-quarter). grid 64*4=256. 64 out cols per CTA.
// ---------------------------------------------------------------------------
__global__ __launch_bounds__(NTHR)
void head_p1(const float* __restrict__ b1) {
    extern __shared__ uint8_t raw[];
    const uint32_t base = sptr(raw);
    __shared__ float sb[TILE];
    int tid = threadIdx.x, wid = tid >> 5, lane = tid & 31;
    int t = blockIdx.x >> 2, jq = blockIdx.x & 3;
    int row0 = t * TILE;

    cpa_copy(base + P1_WH, g_W1T[0] + jq * 64 * S128B, 17408, tid);
    cpa_copy(base + P1_WL, g_W1T[1] + jq * 64 * S128B, 17408, tid);
    cpa_commit();
    if (tid < TILE) sb[tid] = b1[jq * 64 + tid];

    for (int i = tid; i < TILE * 64; i += NTHR) {
        int r = i >> 6, k = i & 63;
        sts32(base + P1_AH + r * S128B + k * 4, g_Xpair[0][(row0 + r) * 64 + k]);
        sts32(base + P1_AL + r * S128B + k * 4, g_Xpair[1][(row0 + r) * 64 + k]);
    }
    cpa_wait0();
    __syncthreads();

    const int mh = wid >> 2, nq = wid & 3;
    const int g = lane >> 2, cp = (lane & 3) * 2;
    float acc[2 * 2 * 4];
#pragma unroll
    for (int i = 0; i < 16; i++) acc[i] = 0.f;
    wgemm<2, 8, S128B, S128B>(acc, base + P1_AH, base + P1_AL,
                              base + P1_WH, base + P1_WL, mh * 32, nq * 16, lane);

    uint8_t* HD0 = g_Himg[0] + t * HIMG + jq * 128;
    uint8_t* HD1 = g_Himg[1] + t * HIMG + jq * 128;
#pragma unroll
    for (int ms = 0; ms < 2; ms++)
#pragma unroll
        for (int nt = 0; nt < 2; nt++) {
            int r0 = mh * 32 + ms * 16 + g;
            int cl = nq * 16 + nt * 8 + cp;
            float* c = acc + (ms * 2 + nt) * 4;
            uint32_t hh, ll;
            splitf(fmaxf(c[0] + sb[cl], 0.f), fmaxf(c[1] + sb[cl + 1], 0.f), hh, ll);
            *(uint32_t*)(HD0 + (size_t)r0 * S256B + cl * 2) = hh;
            *(uint32_t*)(HD1 + (size_t)r0 * S256B + cl * 2) = ll;
            splitf(fmaxf(c[2] + sb[cl], 0.f), fmaxf(c[3] + sb[cl + 1], 0.f), hh, ll);
            *(uint32_t*)(HD0 + (size_t)(r0 + 8) * S256B + cl * 2) = hh;
            *(uint32_t*)(HD1 + (size_t)(r0 + 8) * S256B + cl * 2) = ll;
        }
}

// ---------------------------------------------------------------------------
// Head P2: out tile = H @ W2 + b2. grid = 64.
// ---------------------------------------------------------------------------
__global__ __launch_bounds__(NTHR)
void head_p2(const float* __restrict__ b2, float* __restrict__ out) {
    extern __shared__ uint8_t raw[];
    const uint32_t base = sptr(raw);
    __shared__ float sb2[CDIM];
    int tid = threadIdx.x, wid = tid >> 5, lane = tid & 31;
    int t = blockIdx.x;
    int row0 = t * TILE;

    cpa_copy(base + HP2_HH, g_Himg[0] + t * HIMG, HIMG, tid);
    cpa_copy(base + HP2_HL, g_Himg[1] + t * HIMG, HIMG, tid);
    cpa_copy(base + HP2_WH, g_W2T[0], 8448, tid);
    cpa_copy(base + HP2_WL, g_W2T[1], 8448, tid);
    cpa_commit();
    if (tid < CDIM) sb2[tid] = b2[tid];
    cpa_wait0();
    __syncthreads();

    if (wid < 4) {
        const int mh = wid >> 1, nq = wid & 1;
        const int g = lane >> 2, cp = (lane & 3) * 2;
        float acc[2 * 1 * 4];
#pragma unroll
        for (int i = 0; i < 8; i++) acc[i] = 0.f;
        wgemm<1, 16, S256B, S256B>(acc, base + HP2_HH, base + HP2_HL,
                                   base + HP2_WH, base + HP2_WL, mh * 32, nq * 8, lane);
#pragma unroll
        for (int ms = 0; ms < 2; ms++) {
            int r = row0 + mh * 32 + ms * 16 + g;
            int c0 = nq * 8 + cp;
            float* c = acc + ms * 4;
            out[r * CDIM + c0]           = c[0] + sb2[c0];
            out[r * CDIM + c0 + 1]       = c[1] + sb2[c0 + 1];
            out[(r + 8) * CDIM + c0]     = c[2] + sb2[c0];
            out[(r + 8) * CDIM + c0 + 1] = c[3] + sb2[c0 + 1];
        }
    }
}

// ---------------------------------------------------------------------------
extern "C" void kernel_launch(void* const* d_in, const int* in_sizes, int n_in,
                              void* d_out, int out_size) {
    const int*   entity_ids = (const int*)d_in[0];
    const int*   module_ids = (const int*)d_in[1];
    const float* emb        = (const float*)d_in[2];
    const float* W_in       = (const float*)d_in[3];
    const float* b_in       = (const float*)d_in[4];
    const float* W_bias     = (const float*)d_in[5];
    const float* b_bias     = (const float*)d_in[6];
    const float* W_f        = (const float*)d_in[7];
    const float* b_f        = (const float*)d_in[8];
    const float* W1         = (const float*)d_in[9];
    const float* b1         = (const float*)d_in[10];
    const float* W2         = (const float*)d_in[11];
    const float* b2         = (const float*)d_in[12];
    float* out = (float*)d_out;

    cudaFuncSetAttribute(step_p1, cudaFuncAttributeMaxDynamicSharedMemorySize, P1_SMEM);
    cudaFuncSetAttribute(step_p2, cudaFuncAttributeMaxDynamicSharedMemorySize, P2_SMEM);
    cudaFuncSetAttribute(head_p1, cudaFuncAttributeMaxDynamicSharedMemorySize, P1_SMEM);
    cudaFuncSetAttribute(head_p2, cudaFuncAttributeMaxDynamicSharedMemorySize, HP2_SMEM);

    setup_kernel<<<NSTEPS, NTHR>>>(module_ids);
    xform_kernel<<<dim3(32, 26), NTHR>>>(W_in, W_bias, W_f, W1, W2);
    for (int s = 0; s < NSTEPS; s++) {
        step_p1<<<4 * MAXT, NTHR, P1_SMEM>>>(s, emb, entity_ids, b_in, b_bias);
        step_p2<<<4 * MAXT, NTHR, P2_SMEM>>>(s, b_f);
    }
    head_p1<<<4 * (BB / TILE), NTHR, P1_SMEM>>>(b1);
    head_p2<<<BB / TILE, NTHR, HP2_SMEM>>>(b2, out);
}

// round 12
// speedup vs baseline: 1.4775x; 1.4775x over previous
#include <cuda_runtime.h>
#include <cuda_bf16.h>
#include <math.h>
#include <stdint.h>

#define BB 4096
#define EE 128
#define MMOD 8
#define NSTEPS 3
#define HDIM 256
#define CDIM 16
#define TILE 64
#define NTHR 256
#define MAXT 72

#define S128B 272   // row stride (bytes), K=128 bf16 images
#define S256B 528   // row stride, K=256 images
#define HIMG  33792 // one 64x256 bf16 image (64*528)

// P1 smem: A hi/lo + W hi/lo
#define P1_AH 0
#define P1_AL 17408
#define P1_WH 34816
#define P1_WL 69632
#define P1_SMEM 104448
// P2 smem: H hi/lo + Wf-half hi/lo
#define P2_HH 0
#define P2_HL 33792
#define P2_WH 67584
#define P2_WL 101376
#define P2_SMEM 135168
// head P2 smem
#define HP2_HH 0
#define HP2_HL 33792
#define HP2_WH 67584
#define HP2_WL 76032
#define HP2_SMEM 84480

// ---------------- global scratch ------------------------------------------
__device__ uint32_t g_Xpair[2][BB * 64];            // state: packed bf16 hi/lo
__device__ int g_order[NSTEPS * BB];
__device__ int g_tiles[NSTEPS * MAXT * 3];
__device__ __align__(256) uint8_t g_Himg[2][MAXT * HIMG];   // per-tile H images
__device__ __align__(256) uint8_t g_WinT[2][MMOD * 34816];  // [o=128][e=128]
__device__ __align__(256) uint8_t g_WbiT[2][MMOD * 34816];
__device__ __align__(256) uint8_t g_WfT [2][MMOD * 67584];  // [o=128][f=256]
__device__ __align__(256) uint8_t g_W1T [2][69632];         // [j=256][e=128]
__device__ __align__(256) uint8_t g_W2T [2][8448];          // [c=16][j=256]

// ---------------- helpers ---------------------------------------------------
__device__ __forceinline__ uint32_t sptr(const void* p) {
    return (uint32_t)__cvta_generic_to_shared(p);
}
__device__ __forceinline__ void sts32(uint32_t a, uint32_t v) {
    asm volatile("st.shared.b32 [%0], %1;" :: "r"(a), "r"(v) : "memory");
}
__device__ __forceinline__ void cpa16(uint32_t s, const void* g) {
    asm volatile("cp.async.ca.shared.global [%0], [%1], 16;" :: "r"(s), "l"(g));
}
__device__ __forceinline__ void cpa_commit() { asm volatile("cp.async.commit_group;"); }
__device__ __forceinline__ void cpa_wait0()  { asm volatile("cp.async.wait_group 0;"); }
__device__ __forceinline__ void cpa_copy(uint32_t dst, const uint8_t* src, int bytes, int tid) {
    for (int off = tid * 16; off < bytes; off += NTHR * 16) cpa16(dst + off, src + off);
}
__device__ __forceinline__ void splitf(float v0, float v1, uint32_t& h, uint32_t& l) {
    __nv_bfloat16 h0 = __float2bfloat16(v0), h1 = __float2bfloat16(v1);
    float r0 = v0 - __bfloat162float(h0), r1 = v1 - __bfloat162float(h1);
    __nv_bfloat16 l0 = __float2bfloat16(r0), l1 = __float2bfloat16(r1);
    h = (uint32_t)__bfloat16_as_ushort(h0) | ((uint32_t)__bfloat16_as_ushort(h1) << 16);
    l = (uint32_t)__bfloat16_as_ushort(l0) | ((uint32_t)__bfloat16_as_ushort(l1) << 16);
}
__device__ __forceinline__ void ldsm4(uint32_t* a, uint32_t addr) {
    asm volatile("ldmatrix.sync.aligned.m8n8.x4.shared.b16 {%0,%1,%2,%3}, [%4];"
                 : "=r"(a[0]), "=r"(a[1]), "=r"(a[2]), "=r"(a[3]) : "r"(addr));
}
__device__ __forceinline__ void ldsm2(uint32_t& b0, uint32_t& b1, uint32_t addr) {
    asm volatile("ldmatrix.sync.aligned.m8n8.x2.shared.b16 {%0,%1}, [%2];"
                 : "=r"(b0), "=r"(b1) : "r"(addr));
}
__device__ __forceinline__ void mma4(float* c, const uint32_t* a, uint32_t b0, uint32_t b1) {
    asm volatile("mma.sync.aligned.m16n8k16.row.col.f32.bf16.bf16.f32 "
                 "{%0,%1,%2,%3},{%4,%5,%6,%7},{%8,%9},{%0,%1,%2,%3};"
                 : "+f"(c[0]), "+f"(c[1]), "+f"(c[2]), "+f"(c[3])
                 : "r"(a[0]), "r"(a[1]), "r"(a[2]), "r"(a[3]), "r"(b0), "r"(b1));
}

// Fragment-reuse warp GEMM, 3-term hi/lo split (Ah*Bh + Ah*Bl + Al*Bh).
// Loads Ah/Al once per k-step, Bh/Bl once per (nt,k); all 3 MMAs from regs.
// acc layout: [ms(2)][nt(NT)][4]. M stripes mbase, mbase+16.
template<int NT, int KS, int SBA, int SBB>
__device__ __forceinline__ void wgemm(float* acc,
                                      uint32_t aHI, uint32_t aLO,
                                      uint32_t bHI, uint32_t bLO,
                                      int mbase, int nbase, int lane) {
    const uint32_t aoff = (uint32_t)(mbase + (lane & 15)) * SBA + ((lane >> 4) * 16);
    const uint32_t boff = (uint32_t)(nbase + (lane & 7)) * SBB + (((lane >> 3) & 1) * 16);
    const uint32_t AH = aHI + aoff, AL = aLO + aoff;
    const uint32_t BH = bHI + boff, BL = bLO + boff;
#pragma unroll
    for (int k = 0; k < KS; k++) {
        uint32_t ah0[4], ah1[4], al0[4], al1[4];
        ldsm4(ah0, AH + k * 32);
        ldsm4(ah1, AH + 16 * SBA + k * 32);
        ldsm4(al0, AL + k * 32);
        ldsm4(al1, AL + 16 * SBA + k * 32);
#pragma unroll
        for (int nt = 0; nt < NT; nt++) {
            uint32_t bh0, bh1, bl0, bl1;
            ldsm2(bh0, bh1, BH + nt * 8 * SBB + k * 32);
            ldsm2(bl0, bl1, BL + nt * 8 * SBB + k * 32);
            float* c0 = acc + (0 * NT + nt) * 4;
            float* c1 = acc + (1 * NT + nt) * 4;
            mma4(c0, ah0, bh0, bh1);
            mma4(c1, ah1, bh0, bh1);
            mma4(c0, ah0, bl0, bl1);
            mma4(c1, ah1, bl0, bl1);
            mma4(c0, al0, bh0, bh1);
            mma4(c1, al1, bh0, bh1);
        }
    }
}

// ---------------------------------------------------------------------------
__global__ void setup_kernel(const int* __restrict__ module_ids) {
    __shared__ int cnt[MMOD], cur[MMOD];
    int tid = threadIdx.x, s = blockIdx.x;
    if (tid < MMOD) cnt[tid] = 0;
    __syncthreads();
    for (int b = tid; b < BB; b += NTHR)
        atomicAdd(&cnt[module_ids[b * NSTEPS + s]], 1);
    __syncthreads();
    if (tid == 0) {
        int o = 0, t = 0;
        for (int m = 0; m < MMOD; m++) {
            cur[m] = o;
            int c = cnt[m];
            for (int ch = 0; ch < c; ch += TILE) {
                g_tiles[(s * MAXT + t) * 3 + 0] = m;
                g_tiles[(s * MAXT + t) * 3 + 1] = o + ch;
                g_tiles[(s * MAXT + t) * 3 + 2] = min(TILE, c - ch);
                t++;
            }
            o += c;
        }
        for (; t < MAXT; t++) g_tiles[(s * MAXT + t) * 3 + 2] = 0;
    }
    __syncthreads();
    for (int b = tid; b < BB; b += NTHR) {
        int m = module_ids[b * NSTEPS + s];
        int p = atomicAdd(&cur[m], 1);
        g_order[s * BB + p] = b;
    }
}

__global__ void xform_kernel(const float* __restrict__ W_in,
                             const float* __restrict__ W_bias,
                             const float* __restrict__ W_f,
                             const float* __restrict__ W1,
                             const float* __restrict__ W2) {
    int j = blockIdx.y;
    const float* src; uint8_t *dh, *dl; int R, C, SB;
    if (j < 8)       { src = W_in + j * 16384;  dh = g_WinT[0] + j * 34816; dl = g_WinT[1] + j * 34816; R = 128; C = 128; SB = S128B; }
    else if (j < 16) { int q = j - 8;  src = W_bias + q * 16384; dh = g_WbiT[0] + q * 34816; dl = g_WbiT[1] + q * 34816; R = 128; C = 128; SB = S128B; }
    else if (j < 24) { int q = j - 16; src = W_f + q * 32768;    dh = g_WfT[0] + q * 67584;  dl = g_WfT[1] + q * 67584;  R = 128; C = 256; SB = S256B; }
    else if (j == 24){ src = W1; dh = g_W1T[0]; dl = g_W1T[1]; R = 256; C = 128; SB = S128B; }
    else             { src = W2; dh = g_W2T[0]; dl = g_W2T[1]; R = 16;  C = 256; SB = S256B; }
    int units = R * C / 2;
    for (int u = blockIdx.x * NTHR + threadIdx.x; u < units; u += gridDim.x * NTHR) {
        int rr = u % R, cc = (u / R) * 2;
        float v0 = src[(size_t)cc * R + rr];
        float v1 = src[(size_t)(cc + 1) * R + rr];
        uint32_t h, l;
        splitf(v0, v1, h, l);
        *(uint32_t*)(dh + (size_t)rr * SB + cc * 2) = h;
        *(uint32_t*)(dl + (size_t)rr * SB + cc * 2) = l;
    }
}

// ---------------------------------------------------------------------------
// Step P1: CTA = (tile, half). half 0: Hin = relu(X@Wi+bi); half 1: Hbi.
// Writes its 128 columns of the tile's H image. grid 144.
// ---------------------------------------------------------------------------
__global__ __launch_bounds__(NTHR)
void step_p1(int s, const float* __restrict__ emb, const int* __restrict__ eids,
             const float* __restrict__ b_in, const float* __restrict__ b_bias) {
    extern __shared__ uint8_t raw[];
    const uint32_t base = sptr(raw);
    __shared__ int srow[TILE];
    __shared__ float sb[EE];
    int tid = threadIdx.x, wid = tid >> 5, lane = tid & 31;
    int t = blockIdx.x >> 1, h = blockIdx.x & 1;

    int m   = g_tiles[(s * MAXT + t) * 3 + 0];
    int bse = g_tiles[(s * MAXT + t) * 3 + 1];
    int cnt = g_tiles[(s * MAXT + t) * 3 + 2];
    if (cnt == 0) return;

    const uint8_t* WH = (h ? g_WbiT[0] : g_WinT[0]) + m * 34816;
    const uint8_t* WL = (h ? g_WbiT[1] : g_WinT[1]) + m * 34816;
    cpa_copy(base + P1_WH, WH, 34816, tid);
    cpa_copy(base + P1_WL, WL, 34816, tid);
    cpa_commit();

    if (tid < TILE) {
        int row = g_order[s * BB + bse + (tid < cnt ? tid : 0)];
        srow[tid] = h ? eids[row * (NSTEPS + 1) + s + 1]
                      : ((s == 0) ? eids[row * (NSTEPS + 1)] : row);
    }
    if (tid < EE) sb[tid] = h ? b_bias[m * EE + tid] : b_in[m * EE + tid];
    __syncthreads();

    const bool frompair = (h == 0 && s > 0);
    for (int i = tid; i < TILE * 64; i += NTHR) {
        int r = i >> 6, k = i & 63;
        uint32_t hh, ll;
        if (frompair) {
            hh = g_Xpair[0][srow[r] * 64 + k];
            ll = g_Xpair[1][srow[r] * 64 + k];
        } else {
            float2 v = *(const float2*)&emb[(size_t)srow[r] * EE + 2 * k];
            splitf(v.x, v.y, hh, ll);
        }
        sts32(base + P1_AH + r * S128B + k * 4, hh);
        sts32(base + P1_AL + r * S128B + k * 4, ll);
    }
    cpa_wait0();
    __syncthreads();

    const int mh = wid >> 2, nq = wid & 3;
    const int g = lane >> 2, cp = (lane & 3) * 2;
    float acc[2 * 4 * 4];
#pragma unroll
    for (int i = 0; i < 32; i++) acc[i] = 0.f;
    wgemm<4, 8, S128B, S128B>(acc, base + P1_AH, base + P1_AL,
                              base + P1_WH, base + P1_WL, mh * 32, nq * 32, lane);

    uint8_t* HD0 = g_Himg[0] + t * HIMG + h * 256;   // col offset h*128 cols * 2B
    uint8_t* HD1 = g_Himg[1] + t * HIMG + h * 256;
#pragma unroll
    for (int ms = 0; ms < 2; ms++)
#pragma unroll
        for (int nt = 0; nt < 4; nt++) {
            int r0 = mh * 32 + ms * 16 + g;
            int cw = nq * 32 + nt * 8 + cp;
            float* c = acc + (ms * 4 + nt) * 4;
            uint32_t hh, ll;
            splitf(fmaxf(c[0] + sb[cw], 0.f), fmaxf(c[1] + sb[cw + 1], 0.f), hh, ll);
            *(uint32_t*)(HD0 + (size_t)r0 * S256B + cw * 2) = hh;
            *(uint32_t*)(HD1 + (size_t)r0 * S256B + cw * 2) = ll;
            splitf(fmaxf(c[2] + sb[cw], 0.f), fmaxf(c[3] + sb[cw + 1], 0.f), hh, ll);
            *(uint32_t*)(HD0 + (size_t)(r0 + 8) * S256B + cw * 2) = hh;
            *(uint32_t*)(HD1 + (size_t)(r0 + 8) * S256B + cw * 2) = ll;
        }
}

// ---------------------------------------------------------------------------
// Step P2: CTA = (tile, N-half). x'[:, nh*64:+64] = tanh(H @ WfT_half + b_f).
// grid 144.
// ---------------------------------------------------------------------------
__global__ __launch_bounds__(NTHR)
void step_p2(int s, const float* __restrict__ b_f) {
    extern __shared__ uint8_t raw[];
    const uint32_t base = sptr(raw);
    __shared__ int ridx[TILE];
    __shared__ float sb[TILE];
    int tid = threadIdx.x, wid = tid >> 5, lane = tid & 31;
    int t = blockIdx.x >> 1, nh = blockIdx.x & 1;

    int m   = g_tiles[(s * MAXT + t) * 3 + 0];
    int bse = g_tiles[(s * MAXT + t) * 3 + 1];
    int cnt = g_tiles[(s * MAXT + t) * 3 + 2];
    if (cnt == 0) return;

    cpa_copy(base + P2_HH, g_Himg[0] + t * HIMG, HIMG, tid);
    cpa_copy(base + P2_HL, g_Himg[1] + t * HIMG, HIMG, tid);
    cpa_copy(base + P2_WH, g_WfT[0] + m * 67584 + nh * 33792, 33792, tid);
    cpa_copy(base + P2_WL, g_WfT[1] + m * 67584 + nh * 33792, 33792, tid);
    cpa_commit();

    if (tid < TILE) {
        ridx[tid] = g_order[s * BB + bse + (tid < cnt ? tid : 0)];
        sb[tid] = b_f[m * EE + nh * 64 + tid];
    }
    cpa_wait0();
    __syncthreads();

    const int mh = wid >> 2, nq = wid & 3;
    const int g = lane >> 2, cp = (lane & 3) * 2;
    float acc[2 * 2 * 4];
#pragma unroll
    for (int i = 0; i < 16; i++) acc[i] = 0.f;
    wgemm<2, 16, S256B, S256B>(acc, base + P2_HH, base + P2_HL,
                               base + P2_WH, base + P2_WL, mh * 32, nq * 16, lane);

#pragma unroll
    for (int ms = 0; ms < 2; ms++)
#pragma unroll
        for (int nt = 0; nt < 2; nt++) {
            int r0 = mh * 32 + ms * 16 + g;
            int cl = nq * 16 + nt * 8 + cp;        // local col 0..63
            int cg = nh * 64 + cl;                 // global feature col
            float* c = acc + (ms * 2 + nt) * 4;
            uint32_t hh, ll;
            if (r0 < cnt) {
                int gr = ridx[r0];
                splitf(tanhf(c[0] + sb[cl]), tanhf(c[1] + sb[cl + 1]), hh, ll);
                g_Xpair[0][gr * 64 + (cg >> 1)] = hh;
                g_Xpair[1][gr * 64 + (cg >> 1)] = ll;
            }
            if (r0 + 8 < cnt) {
                int gr = ridx[r0 + 8];
                splitf(tanhf(c[2] + sb[cl]), tanhf(c[3] + sb[cl + 1]), hh, ll);
                g_Xpair[0][gr * 64 + (cg >> 1)] = hh;
                g_Xpair[1][gr * 64 + (cg >> 1)] = ll;
            }
        }
}

// ---------------------------------------------------------------------------
// Head P1: CTA = (tile, j-half). H[:, h*128:+128] = relu(X @ W1T_half + b1).
// grid 128.
// ---------------------------------------------------------------------------
__global__ __launch_bounds__(NTHR)
void head_p1(const float* __restrict__ b1) {
    extern __shared__ uint8_t raw[];
    const uint32_t base = sptr(raw);
    __shared__ float sb[EE];
    int tid = threadIdx.x, wid = tid >> 5, lane = tid & 31;
    int t = blockIdx.x >> 1, h = blockIdx.x & 1;
    int row0 = t * TILE;

    cpa_copy(base + P1_WH, g_W1T[0] + h * 34816, 34816, tid);
    cpa_copy(base + P1_WL, g_W1T[1] + h * 34816, 34816, tid);
    cpa_commit();
    if (tid < EE) sb[tid] = b1[h * EE + tid];

    for (int i = tid; i < TILE * 64; i += NTHR) {
        int r = i >> 6, k = i & 63;
        sts32(base + P1_AH + r * S128B + k * 4, g_Xpair[0][(row0 + r) * 64 + k]);
        sts32(base + P1_AL + r * S128B + k * 4, g_Xpair[1][(row0 + r) * 64 + k]);
    }
    cpa_wait0();
    __syncthreads();

    const int mh = wid >> 2, nq = wid & 3;
    const int g = lane >> 2, cp = (lane & 3) * 2;
    float acc[2 * 4 * 4];
#pragma unroll
    for (int i = 0; i < 32; i++) acc[i] = 0.f;
    wgemm<4, 8, S128B, S128B>(acc, base + P1_AH, base + P1_AL,
                              base + P1_WH, base + P1_WL, mh * 32, nq * 32, lane);

    uint8_t* HD0 = g_Himg[0] + t * HIMG + h * 256;
    uint8_t* HD1 = g_Himg[1] + t * HIMG + h * 256;
#pragma unroll
    for (int ms = 0; ms < 2; ms++)
#pragma unroll
        for (int nt = 0; nt < 4; nt++) {
            int r0 = mh * 32 + ms * 16 + g;
            int cw = nq * 32 + nt * 8 + cp;
            float* c = acc + (ms * 4 + nt) * 4;
            uint32_t hh, ll;
            splitf(fmaxf(c[0] + sb[cw], 0.f), fmaxf(c[1] + sb[cw + 1], 0.f), hh, ll);
            *(uint32_t*)(HD0 + (size_t)r0 * S256B + cw * 2) = hh;
            *(uint32_t*)(HD1 + (size_t)r0 * S256B + cw * 2) = ll;
            splitf(fmaxf(c[2] + sb[cw], 0.f), fmaxf(c[3] + sb[cw + 1], 0.f), hh, ll);
            *(uint32_t*)(HD0 + (size_t)(r0 + 8) * S256B + cw * 2) = hh;
            *(uint32_t*)(HD1 + (size_t)(r0 + 8) * S256B + cw * 2) = ll;
        }
}

// ---------------------------------------------------------------------------
// Head P2: out tile = H @ W2 + b2. grid = 64 tiles.
// ---------------------------------------------------------------------------
__global__ __launch_bounds__(NTHR)
void head_p2(const float* __restrict__ b2, float* __restrict__ out) {
    extern __shared__ uint8_t raw[];
    const uint32_t base = sptr(raw);
    __shared__ float sb2[CDIM];
    int tid = threadIdx.x, wid = tid >> 5, lane = tid & 31;
    int t = blockIdx.x;
    int row0 = t * TILE;

    cpa_copy(base + HP2_HH, g_Himg[0] + t * HIMG, HIMG, tid);
    cpa_copy(base + HP2_HL, g_Himg[1] + t * HIMG, HIMG, tid);
    cpa_copy(base + HP2_WH, g_W2T[0], 8448, tid);
    cpa_copy(base + HP2_WL, g_W2T[1], 8448, tid);
    cpa_commit();
    if (tid < CDIM) sb2[tid] = b2[tid];
    cpa_wait0();
    __syncthreads();

    if (wid < 4) {
        const int mh = wid >> 1, nq = wid & 1;
        const int g = lane >> 2, cp = (lane & 3) * 2;
        float acc[2 * 1 * 4];
#pragma unroll
        for (int i = 0; i < 8; i++) acc[i] = 0.f;
        wgemm<1, 16, S256B, S256B>(acc, base + HP2_HH, base + HP2_HL,
                                   base + HP2_WH, base + HP2_WL, mh * 32, nq * 8, lane);
#pragma unroll
        for (int ms = 0; ms < 2; ms++) {
            int r = row0 + mh * 32 + ms * 16 + g;
            int c0 = nq * 8 + cp;
            float* c = acc + ms * 4;
            out[r * CDIM + c0]           = c[0] + sb2[c0];
            out[r * CDIM + c0 + 1]       = c[1] + sb2[c0 + 1];
            out[(r + 8) * CDIM + c0]     = c[2] + sb2[c0];
            out[(r + 8) * CDIM + c0 + 1] = c[3] + sb2[c0 + 1];
        }
    }
}

// ---------------------------------------------------------------------------
extern "C" void kernel_launch(void* const* d_in, const int* in_sizes, int n_in,
                              void* d_out, int out_size) {
    const int*   entity_ids = (const int*)d_in[0];
    const int*   module_ids = (const int*)d_in[1];
    const float* emb        = (const float*)d_in[2];
    const float* W_in       = (const float*)d_in[3];
    const float* b_in       = (const float*)d_in[4];
    const float* W_bias     = (const float*)d_in[5];
    const float* b_bias     = (const float*)d_in[6];
    const float* W_f        = (const float*)d_in[7];
    const float* b_f        = (const float*)d_in[8];
    const float* W1         = (const float*)d_in[9];
    const float* b1         = (const float*)d_in[10];
    const float* W2         = (const float*)d_in[11];
    const float* b2         = (const float*)d_in[12];
    float* out = (float*)d_out;

    cudaFuncSetAttribute(step_p1, cudaFuncAttributeMaxDynamicSharedMemorySize, P1_SMEM);
    cudaFuncSetAttribute(step_p2, cudaFuncAttributeMaxDynamicSharedMemorySize, P2_SMEM);
    cudaFuncSetAttribute(head_p1, cudaFuncAttributeMaxDynamicSharedMemorySize, P1_SMEM);
    cudaFuncSetAttribute(head_p2, cudaFuncAttributeMaxDynamicSharedMemorySize, HP2_SMEM);

    setup_kernel<<<NSTEPS, NTHR>>>(module_ids);
    xform_kernel<<<dim3(32, 26), NTHR>>>(W_in, W_bias, W_f, W1, W2);
    for (int s = 0; s < NSTEPS; s++) {
        step_p1<<<2 * MAXT, NTHR, P1_SMEM>>>(s, emb, entity_ids, b_in, b_bias);
        step_p2<<<2 * MAXT, NTHR, P2_SMEM>>>(s, b_f);
    }
    head_p1<<<2 * (BB / TILE), NTHR, P1_SMEM>>>(b1);
    head_p2<<<BB / TILE, NTHR, HP2_SMEM>>>(b2, out);
}

// round 14
// speedup vs baseline: 1.6476x; 1.1151x over previous
#include <cuda_runtime.h>
#include <cuda_bf16.h>
#include <math.h>
#include <stdint.h>

#define BB 4096
#define EE 128
#define MMOD 8
#define NSTEPS 3
#define HDIM 256
#define CDIM 16
#define TILE 64
#define NTHR 256
#define NTHR2 512
#define MAXT 72

#define S128B 272   // row stride (bytes), K=128 bf16 images
#define S256B 528   // row stride, K=256 images
#define HIMG  33792 // one 64x256 bf16 image (64*528)

// P1 smem: A hi/lo + W hi/lo
#define P1_AH 0
#define P1_AL 17408
#define P1_WH 34816
#define P1_WL 69632
#define P1_SMEM 104448
// P2 smem: H hi/lo + Wf-half hi/lo
#define P2_HH 0
#define P2_HL 33792
#define P2_WH 67584
#define P2_WL 101376
#define P2_SMEM 135168
// head P2 smem
#define HP2_HH 0
#define HP2_HL 33792
#define HP2_WH 67584
#define HP2_WL 76032
#define HP2_SMEM 84480

// ---------------- global scratch ------------------------------------------
__device__ uint32_t g_Xpair[2][BB * 64];            // state: packed bf16 hi/lo
__device__ int g_order[NSTEPS * BB];
__device__ int g_tiles[NSTEPS * MAXT * 3];
__device__ __align__(256) uint8_t g_Himg[2][MAXT * HIMG];   // per-tile H images
__device__ __align__(256) uint8_t g_WinT[2][MMOD * 34816];  // [o=128][e=128]
__device__ __align__(256) uint8_t g_WbiT[2][MMOD * 34816];
__device__ __align__(256) uint8_t g_WfT [2][MMOD * 67584];  // [o=128][f=256]
__device__ __align__(256) uint8_t g_W1T [2][69632];         // [j=256][e=128]
__device__ __align__(256) uint8_t g_W2T [2][8448];          // [c=16][j=256]

// ---------------- helpers ---------------------------------------------------
__device__ __forceinline__ uint32_t sptr(const void* p) {
    return (uint32_t)__cvta_generic_to_shared(p);
}
__device__ __forceinline__ void sts32(uint32_t a, uint32_t v) {
    asm volatile("st.shared.b32 [%0], %1;" :: "r"(a), "r"(v) : "memory");
}
__device__ __forceinline__ void cpa16(uint32_t s, const void* g) {
    asm volatile("cp.async.ca.shared.global [%0], [%1], 16;" :: "r"(s), "l"(g));
}
__device__ __forceinline__ void cpa_commit() { asm volatile("cp.async.commit_group;"); }
template<int N>
__device__ __forceinline__ void cpa_wait() {
    asm volatile("cp.async.wait_group %0;" :: "n"(N));
}
__device__ __forceinline__ void cpa_copy(uint32_t dst, const uint8_t* src, int bytes,
                                         int tid, int nthr) {
    for (int off = tid * 16; off < bytes; off += nthr * 16) cpa16(dst + off, src + off);
}
// copy byte-column slice [c0, c0+cb) of an image with row stride SB (same layout smem/gmem)
__device__ __forceinline__ void cpa_copy_cols(uint32_t dst, const uint8_t* src,
                                              int rows, int SB, int c0, int cb,
                                              int tid, int nthr) {
    int units = rows * (cb >> 4);
    for (int i = tid; i < units; i += nthr) {
        int r = i / (cb >> 4), o = (i % (cb >> 4)) * 16;
        uint32_t off = (uint32_t)r * SB + c0 + o;
        cpa16(dst + off, src + off);
    }
}
__device__ __forceinline__ void splitf(float v0, float v1, uint32_t& h, uint32_t& l) {
    __nv_bfloat16 h0 = __float2bfloat16(v0), h1 = __float2bfloat16(v1);
    float r0 = v0 - __bfloat162float(h0), r1 = v1 - __bfloat162float(h1);
    __nv_bfloat16 l0 = __float2bfloat16(r0), l1 = __float2bfloat16(r1);
    h = (uint32_t)__bfloat16_as_ushort(h0) | ((uint32_t)__bfloat16_as_ushort(h1) << 16);
    l = (uint32_t)__bfloat16_as_ushort(l0) | ((uint32_t)__bfloat16_as_ushort(l1) << 16);
}
__device__ __forceinline__ void ldsm4(uint32_t* a, uint32_t addr) {
    asm volatile("ldmatrix.sync.aligned.m8n8.x4.shared.b16 {%0,%1,%2,%3}, [%4];"
                 : "=r"(a[0]), "=r"(a[1]), "=r"(a[2]), "=r"(a[3]) : "r"(addr));
}
__device__ __forceinline__ void ldsm2(uint32_t& b0, uint32_t& b1, uint32_t addr) {
    asm volatile("ldmatrix.sync.aligned.m8n8.x2.shared.b16 {%0,%1}, [%2];"
                 : "=r"(b0), "=r"(b1) : "r"(addr));
}
__device__ __forceinline__ void mma4(float* c, const uint32_t* a, uint32_t b0, uint32_t b1) {
    asm volatile("mma.sync.aligned.m16n8k16.row.col.f32.bf16.bf16.f32 "
                 "{%0,%1,%2,%3},{%4,%5,%6,%7},{%8,%9},{%0,%1,%2,%3};"
                 : "+f"(c[0]), "+f"(c[1]), "+f"(c[2]), "+f"(c[3])
                 : "r"(a[0]), "r"(a[1]), "r"(a[2]), "r"(a[3]), "r"(b0), "r"(b1));
}

// Single-M-stripe (16 rows) fragment-reuse warp GEMM, 3-term hi/lo split.
// KC k-steps (16 cols each) starting at byte offset kb0. acc[NT][4].
template<int NT, int KC, int SBA, int SBB>
__device__ __forceinline__ void wgemm1(float* acc,
                                       uint32_t aHI, uint32_t aLO,
                                       uint32_t bHI, uint32_t bLO,
                                       int mbase, int nbase, int lane, int kb0) {
    const uint32_t aoff = (uint32_t)(mbase + (lane & 15)) * SBA + ((lane >> 4) * 16) + kb0;
    const uint32_t boff = (uint32_t)(nbase + (lane & 7)) * SBB + (((lane >> 3) & 1) * 16) + kb0;
    const uint32_t AH = aHI + aoff, AL = aLO + aoff;
    const uint32_t BH = bHI + boff, BL = bLO + boff;
#pragma unroll
    for (int k = 0; k < KC; k++) {
        uint32_t ah[4], al[4];
        ldsm4(ah, AH + k * 32);
        ldsm4(al, AL + k * 32);
#pragma unroll
        for (int nt = 0; nt < NT; nt++) {
            uint32_t bh0, bh1, bl0, bl1;
            ldsm2(bh0, bh1, BH + nt * 8 * SBB + k * 32);
            ldsm2(bl0, bl1, BL + nt * 8 * SBB + k * 32);
            float* c = acc + nt * 4;
            mma4(c, ah, bh0, bh1);
            mma4(c, ah, bl0, bl1);
            mma4(c, al, bh0, bh1);
        }
    }
}
// Two-M-stripe variant for head_p2.
template<int NT, int KS, int SBA, int SBB>
__device__ __forceinline__ void wgemm(float* acc,
                                      uint32_t aHI, uint32_t aLO,
                                      uint32_t bHI, uint32_t bLO,
                                      int mbase, int nbase, int lane) {
    const uint32_t aoff = (uint32_t)(mbase + (lane & 15)) * SBA + ((lane >> 4) * 16);
    const uint32_t boff = (uint32_t)(nbase + (lane & 7)) * SBB + (((lane >> 3) & 1) * 16);
    const uint32_t AH = aHI + aoff, AL = aLO + aoff;
    const uint32_t BH = bHI + boff, BL = bLO + boff;
#pragma unroll
    for (int k = 0; k < KS; k++) {
        uint32_t ah0[4], ah1[4], al0[4], al1[4];
        ldsm4(ah0, AH + k * 32);
        ldsm4(ah1, AH + 16 * SBA + k * 32);
        ldsm4(al0, AL + k * 32);
        ldsm4(al1, AL + 16 * SBA + k * 32);
#pragma unroll
        for (int nt = 0; nt < NT; nt++) {
            uint32_t bh0, bh1, bl0, bl1;
            ldsm2(bh0, bh1, BH + nt * 8 * SBB + k * 32);
            ldsm2(bl0, bl1, BL + nt * 8 * SBB + k * 32);
            float* c0 = acc + (0 * NT + nt) * 4;
            float* c1 = acc + (1 * NT + nt) * 4;
            mma4(c0, ah0, bh0, bh1);
            mma4(c1, ah1, bh0, bh1);
            mma4(c0, ah0, bl0, bl1);
            mma4(c1, ah1, bl0, bl1);
            mma4(c0, al0, bh0, bh1);
            mma4(c1, al1, bh0, bh1);
        }
    }
}

// ---------------------------------------------------------------------------
__global__ void setup_kernel(const int* __restrict__ module_ids) {
    __shared__ int cnt[MMOD], cur[MMOD];
    int tid = threadIdx.x, s = blockIdx.x;
    if (tid < MMOD) cnt[tid] = 0;
    __syncthreads();
    for (int b = tid; b < BB; b += NTHR)
        atomicAdd(&cnt[module_ids[b * NSTEPS + s]], 1);
    __syncthreads();
    if (tid == 0) {
        int o = 0, t = 0;
        for (int m = 0; m < MMOD; m++) {
            cur[m] = o;
            int c = cnt[m];
            for (int ch = 0; ch < c; ch += TILE) {
                g_tiles[(s * MAXT + t) * 3 + 0] = m;
                g_tiles[(s * MAXT + t) * 3 + 1] = o + ch;
                g_tiles[(s * MAXT + t) * 3 + 2] = min(TILE, c - ch);
                t++;
            }
            o += c;
        }
        for (; t < MAXT; t++) g_tiles[(s * MAXT + t) * 3 + 2] = 0;
    }
    __syncthreads();
    for (int b = tid; b < BB; b += NTHR) {
        int m = module_ids[b * NSTEPS + s];
        int p = atomicAdd(&cur[m], 1);
        g_order[s * BB + p] = b;
    }
}

__global__ void xform_kernel(const float* __restrict__ W_in,
                             const float* __restrict__ W_bias,
                             const float* __restrict__ W_f,
                             const float* __restrict__ W1,
                             const float* __restrict__ W2) {
    int j = blockIdx.y;
    const float* src; uint8_t *dh, *dl; int R, C, SB;
    if (j < 8)       { src = W_in + j * 16384;  dh = g_WinT[0] + j * 34816; dl = g_WinT[1] + j * 34816; R = 128; C = 128; SB = S128B; }
    else if (j < 16) { int q = j - 8;  src = W_bias + q * 16384; dh = g_WbiT[0] + q * 34816; dl = g_WbiT[1] + q * 34816; R = 128; C = 128; SB = S128B; }
    else if (j < 24) { int q = j - 16; src = W_f + q * 32768;    dh = g_WfT[0] + q * 67584;  dl = g_WfT[1] + q * 67584;  R = 128; C = 256; SB = S256B; }
    else if (j == 24){ src = W1; dh = g_W1T[0]; dl = g_W1T[1]; R = 256; C = 128; SB = S128B; }
    else             { src = W2; dh = g_W2T[0]; dl = g_W2T[1]; R = 16;  C = 256; SB = S256B; }
    int units = R * C / 2;
    for (int u = blockIdx.x * NTHR + threadIdx.x; u < units; u += gridDim.x * NTHR) {
        int rr = u % R, cc = (u / R) * 2;
        float v0 = src[(size_t)cc * R + rr];
        float v1 = src[(size_t)(cc + 1) * R + rr];
        uint32_t h, l;
        splitf(v0, v1, h, l);
        *(uint32_t*)(dh + (size_t)rr * SB + cc * 2) = h;
        *(uint32_t*)(dl + (size_t)rr * SB + cc * 2) = l;
    }
}

// ---------------------------------------------------------------------------
// Step P1: CTA = (tile, half). 512 thr, 16 warps: mh(4 x 16 rows) x nq(4 x 32 cols).
// W staged in 2 K-chunks with progressive waits. grid 144.
// ---------------------------------------------------------------------------
__global__ __launch_bounds__(NTHR2)
void step_p1(int s, const float* __restrict__ emb, const int* __restrict__ eids,
             const float* __restrict__ b_in, const float* __restrict__ b_bias) {
    extern __shared__ uint8_t raw[];
    const uint32_t base = sptr(raw);
    __shared__ int srow[TILE];
    __shared__ float sb[EE];
    int tid = threadIdx.x, wid = tid >> 5, lane = tid & 31;
    int t = blockIdx.x >> 1, h = blockIdx.x & 1;

    int m   = g_tiles[(s * MAXT + t) * 3 + 0];
    int bse = g_tiles[(s * MAXT + t) * 3 + 1];
    int cnt = g_tiles[(s * MAXT + t) * 3 + 2];
    if (cnt == 0) return;

    const uint8_t* WH = (h ? g_WbiT[0] : g_WinT[0]) + m * 34816;
    const uint8_t* WL = (h ? g_WbiT[1] : g_WinT[1]) + m * 34816;
    // chunk 0: K cols 0..63 (bytes 0..127); chunk 1: 64..127
    cpa_copy_cols(base + P1_WH, WH, 128, S128B, 0, 128, tid, NTHR2);
    cpa_copy_cols(base + P1_WL, WL, 128, S128B, 0, 128, tid, NTHR2);
    cpa_commit();
    cpa_copy_cols(base + P1_WH, WH, 128, S128B, 128, 128, tid, NTHR2);
    cpa_copy_cols(base + P1_WL, WL, 128, S128B, 128, 128, tid, NTHR2);
    cpa_commit();

    if (tid < TILE) {
        int row = g_order[s * BB + bse + (tid < cnt ? tid : 0)];
        srow[tid] = h ? eids[row * (NSTEPS + 1) + s + 1]
                      : ((s == 0) ? eids[row * (NSTEPS + 1)] : row);
    }
    if (tid < EE) sb[tid] = h ? b_bias[m * EE + tid] : b_in[m * EE + tid];
    __syncthreads();

    const bool frompair = (h == 0 && s > 0);
    for (int i = tid; i < TILE * 64; i += NTHR2) {
        int r = i >> 6, k = i & 63;
        uint32_t hh, ll;
        if (frompair) {
            hh = g_Xpair[0][srow[r] * 64 + k];
            ll = g_Xpair[1][srow[r] * 64 + k];
        } else {
            float2 v = *(const float2*)&emb[(size_t)srow[r] * EE + 2 * k];
            splitf(v.x, v.y, hh, ll);
        }
        sts32(base + P1_AH + r * S128B + k * 4, hh);
        sts32(base + P1_AL + r * S128B + k * 4, ll);
    }

    const int mh = wid >> 2, nq = wid & 3;
    const int g = lane >> 2, cp = (lane & 3) * 2;
    float acc[4 * 4];
#pragma unroll
    for (int i = 0; i < 16; i++) acc[i] = 0.f;

    cpa_wait<1>();
    __syncthreads();
    wgemm1<4, 4, S128B, S128B>(acc, base + P1_AH, base + P1_AL,
                               base + P1_WH, base + P1_WL, mh * 16, nq * 32, lane, 0);
    cpa_wait<0>();
    __syncthreads();
    wgemm1<4, 4, S128B, S128B>(acc, base + P1_AH, base + P1_AL,
                               base + P1_WH, base + P1_WL, mh * 16, nq * 32, lane, 128);

    uint8_t* HD0 = g_Himg[0] + t * HIMG + h * 256;
    uint8_t* HD1 = g_Himg[1] + t * HIMG + h * 256;
#pragma unroll
    for (int nt = 0; nt < 4; nt++) {
        int r0 = mh * 16 + g;
        int cw = nq * 32 + nt * 8 + cp;
        float* c = acc + nt * 4;
        uint32_t hh, ll;
        splitf(fmaxf(c[0] + sb[cw], 0.f), fmaxf(c[1] + sb[cw + 1], 0.f), hh, ll);
        *(uint32_t*)(HD0 + (size_t)r0 * S256B + cw * 2) = hh;
        *(uint32_t*)(HD1 + (size_t)r0 * S256B + cw * 2) = ll;
        splitf(fmaxf(c[2] + sb[cw], 0.f), fmaxf(c[3] + sb[cw + 1], 0.f), hh, ll);
        *(uint32_t*)(HD0 + (size_t)(r0 + 8) * S256B + cw * 2) = hh;
        *(uint32_t*)(HD1 + (size_t)(r0 + 8) * S256B + cw * 2) = ll;
    }
}

// ---------------------------------------------------------------------------
// Step P2: CTA = (tile, N-half). 512 thr, 16 warps: mh(4) x nq(4 x 16 cols).
// H + W staged in 4 K-chunks with progressive waits. grid 144.
// ---------------------------------------------------------------------------
__global__ __launch_bounds__(NTHR2)
void step_p2(int s, const float* __restrict__ b_f) {
    extern __shared__ uint8_t raw[];
    const uint32_t base = sptr(raw);
    __shared__ int ridx[TILE];
    __shared__ float sb[TILE];
    int tid = threadIdx.x, wid = tid >> 5, lane = tid & 31;
    int t = blockIdx.x >> 1, nh = blockIdx.x & 1;

    int m   = g_tiles[(s * MAXT + t) * 3 + 0];
    int bse = g_tiles[(s * MAXT + t) * 3 + 1];
    int cnt = g_tiles[(s * MAXT + t) * 3 + 2];
    if (cnt == 0) return;

    const uint8_t* H0 = g_Himg[0] + t * HIMG;
    const uint8_t* H1 = g_Himg[1] + t * HIMG;
    const uint8_t* W0 = g_WfT[0] + m * 67584 + nh * 33792;
    const uint8_t* W1p = g_WfT[1] + m * 67584 + nh * 33792;
#pragma unroll
    for (int c = 0; c < 4; c++) {
        cpa_copy_cols(base + P2_HH, H0, 64, S256B, c * 128, 128, tid, NTHR2);
        cpa_copy_cols(base + P2_HL, H1, 64, S256B, c * 128, 128, tid, NTHR2);
        cpa_copy_cols(base + P2_WH, W0, 64, S256B, c * 128, 128, tid, NTHR2);
        cpa_copy_cols(base + P2_WL, W1p, 64, S256B, c * 128, 128, tid, NTHR2);
        cpa_commit();
    }

    if (tid < TILE) {
        ridx[tid] = g_order[s * BB + bse + (tid < cnt ? tid : 0)];
        sb[tid] = b_f[m * EE + nh * 64 + tid];
    }

    const int mh = wid >> 2, nq = wid & 3;
    const int g = lane >> 2, cp = (lane & 3) * 2;
    float acc[2 * 4];
#pragma unroll
    for (int i = 0; i < 8; i++) acc[i] = 0.f;

    cpa_wait<3>(); __syncthreads();
    wgemm1<2, 4, S256B, S256B>(acc, base + P2_HH, base + P2_HL,
                               base + P2_WH, base + P2_WL, mh * 16, nq * 16, lane, 0);
    cpa_wait<2>(); __syncthreads();
    wgemm1<2, 4, S256B, S256B>(acc, base + P2_HH, base + P2_HL,
                               base + P2_WH, base + P2_WL, mh * 16, nq * 16, lane, 128);
    cpa_wait<1>(); __syncthreads();
    wgemm1<2, 4, S256B, S256B>(acc, base + P2_HH, base + P2_HL,
                               base + P2_WH, base + P2_WL, mh * 16, nq * 16, lane, 256);
    cpa_wait<0>(); __syncthreads();
    wgemm1<2, 4, S256B, S256B>(acc, base + P2_HH, base + P2_HL,
                               base + P2_WH, base + P2_WL, mh * 16, nq * 16, lane, 384);

#pragma unroll
    for (int nt = 0; nt < 2; nt++) {
        int r0 = mh * 16 + g;
        int cl = nq * 16 + nt * 8 + cp;
        int cg = nh * 64 + cl;
        float* c = acc + nt * 4;
        uint32_t hh, ll;
        if (r0 < cnt) {
            int gr = ridx[r0];
            splitf(tanhf(c[0] + sb[cl]), tanhf(c[1] + sb[cl + 1]), hh, ll);
            g_Xpair[0][gr * 64 + (cg >> 1)] = hh;
            g_Xpair[1][gr * 64 + (cg >> 1)] = ll;
        }
        if (r0 + 8 < cnt) {
            int gr = ridx[r0 + 8];
            splitf(tanhf(c[2] + sb[cl]), tanhf(c[3] + sb[cl + 1]), hh, ll);
            g_Xpair[0][gr * 64 + (cg >> 1)] = hh;
            g_Xpair[1][gr * 64 + (cg >> 1)] = ll;
        }
    }
}

// ---------------------------------------------------------------------------
// Head P1: CTA = (tile, j-half). 512 thr. grid 128.
// W1T half = 128 j-rows (NOT 256 — overflow bug fixed).
// ---------------------------------------------------------------------------
__global__ __launch_bounds__(NTHR2)
void head_p1(const float* __restrict__ b1) {
    extern __shared__ uint8_t raw[];
    const uint32_t base = sptr(raw);
    __shared__ float sb[EE];
    int tid = threadIdx.x, wid = tid >> 5, lane = tid & 31;
    int t = blockIdx.x >> 1, h = blockIdx.x & 1;
    int row0 = t * TILE;

    const uint8_t* WH = g_W1T[0] + h * 34816;
    const uint8_t* WL = g_W1T[1] + h * 34816;
    cpa_copy_cols(base + P1_WH, WH, 128, S128B, 0, 128, tid, NTHR2);
    cpa_copy_cols(base + P1_WL, WL, 128, S128B, 0, 128, tid, NTHR2);
    cpa_commit();
    cpa_copy_cols(base + P1_WH, WH, 128, S128B, 128, 128, tid, NTHR2);
    cpa_copy_cols(base + P1_WL, WL, 128, S128B, 128, 128, tid, NTHR2);
    cpa_commit();
    if (tid < EE) sb[tid] = b1[h * EE + tid];

    for (int i = tid; i < TILE * 64; i += NTHR2) {
        int r = i >> 6, k = i & 63;
        sts32(base + P1_AH + r * S128B + k * 4, g_Xpair[0][(row0 + r) * 64 + k]);
        sts32(base + P1_AL + r * S128B + k * 4, g_Xpair[1][(row0 + r) * 64 + k]);
    }

    const int mh = wid >> 2, nq = wid & 3;
    const int g = lane >> 2, cp = (lane & 3) * 2;
    float acc[4 * 4];
#pragma unroll
    for (int i = 0; i < 16; i++) acc[i] = 0.f;

    cpa_wait<1>();
    __syncthreads();
    wgemm1<4, 4, S128B, S128B>(acc, base + P1_AH, base + P1_AL,
                               base + P1_WH, base + P1_WL, mh * 16, nq * 32, lane, 0);
    cpa_wait<0>();
    __syncthreads();
    wgemm1<4, 4, S128B, S128B>(acc, base + P1_AH, base + P1_AL,
                               base + P1_WH, base + P1_WL, mh * 16, nq * 32, lane, 128);

    uint8_t* HD0 = g_Himg[0] + t * HIMG + h * 256;
    uint8_t* HD1 = g_Himg[1] + t * HIMG + h * 256;
#pragma unroll
    for (int nt = 0; nt < 4; nt++) {
        int r0 = mh * 16 + g;
        int cw = nq * 32 + nt * 8 + cp;
        float* c = acc + nt * 4;
        uint32_t hh, ll;
        splitf(fmaxf(c[0] + sb[cw], 0.f), fmaxf(c[1] + sb[cw + 1], 0.f), hh, ll);
        *(uint32_t*)(HD0 + (size_t)r0 * S256B + cw * 2) = hh;
        *(uint32_t*)(HD1 + (size_t)r0 * S256B + cw * 2) = ll;
        splitf(fmaxf(c[2] + sb[cw], 0.f), fmaxf(c[3] + sb[cw + 1], 0.f), hh, ll);
        *(uint32_t*)(HD0 + (size_t)(r0 + 8) * S256B + cw * 2) = hh;
        *(uint32_t*)(HD1 + (size_t)(r0 + 8) * S256B + cw * 2) = ll;
    }
}

// ---------------------------------------------------------------------------
// Head P2: out tile = H @ W2 + b2. grid = 64 tiles, 256 thr.
// ---------------------------------------------------------------------------
__global__ __launch_bounds__(NTHR)
void head_p2(const float* __restrict__ b2, float* __restrict__ out) {
    extern __shared__ uint8_t raw[];
    const uint32_t base = sptr(raw);
    __shared__ float sb2[CDIM];
    int tid = threadIdx.x, wid = tid >> 5, lane = tid & 31;
    int t = blockIdx.x;
    int row0 = t * TILE;

    cpa_copy(base + HP2_HH, g_Himg[0] + t * HIMG, HIMG, tid, NTHR);
    cpa_copy(base + HP2_HL, g_Himg[1] + t * HIMG, HIMG, tid, NTHR);
    cpa_copy(base + HP2_WH, g_W2T[0], 8448, tid, NTHR);
    cpa_copy(base + HP2_WL, g_W2T[1], 8448, tid, NTHR);
    cpa_commit();
    if (tid < CDIM) sb2[tid] = b2[tid];
    cpa_wait<0>();
    __syncthreads();

    if (wid < 4) {
        const int mh = wid >> 1, nq = wid & 1;
        const int g = lane >> 2, cp = (lane & 3) * 2;
        float acc[2 * 1 * 4];
#pragma unroll
        for (int i = 0; i < 8; i++) acc[i] = 0.f;
        wgemm<1, 16, S256B, S256B>(acc, base + HP2_HH, base + HP2_HL,
                                   base + HP2_WH, base + HP2_WL, mh * 32, nq * 8, lane);
#pragma unroll
        for (int ms = 0; ms < 2; ms++) {
            int r = row0 + mh * 32 + ms * 16 + g;
            int c0 = nq * 8 + cp;
            float* c = acc + ms * 4;
            out[r * CDIM + c0]           = c[0] + sb2[c0];
            out[r * CDIM + c0 + 1]       = c[1] + sb2[c0 + 1];
            out[(r + 8) * CDIM + c0]     = c[2] + sb2[c0];
            out[(r + 8) * CDIM + c0 + 1] = c[3] + sb2[c0 + 1];
        }
    }
}

// ---------------------------------------------------------------------------
extern "C" void kernel_launch(void* const* d_in, const int* in_sizes, int n_in,
                              void* d_out, int out_size) {
    const int*   entity_ids = (const int*)d_in[0];
    const int*   module_ids = (const int*)d_in[1];
    const float* emb        = (const float*)d_in[2];
    const float* W_in       = (const float*)d_in[3];
    const float* b_in       = (const float*)d_in[4];
    const float* W_bias     = (const float*)d_in[5];
    const float* b_bias     = (const float*)d_in[6];
    const float* W_f        = (const float*)d_in[7];
    const float* b_f        = (const float*)d_in[8];
    const float* W1         = (const float*)d_in[9];
    const float* b1         = (const float*)d_in[10];
    const float* W2         = (const float*)d_in[11];
    const float* b2         = (const float*)d_in[12];
    float* out = (float*)d_out;

    cudaFuncSetAttribute(step_p1, cudaFuncAttributeMaxDynamicSharedMemorySize, P1_SMEM);
    cudaFuncSetAttribute(step_p2, cudaFuncAttributeMaxDynamicSharedMemorySize, P2_SMEM);
    cudaFuncSetAttribute(head_p1, cudaFuncAttributeMaxDynamicSharedMemorySize, P1_SMEM);
    cudaFuncSetAttribute(head_p2, cudaFuncAttributeMaxDynamicSharedMemorySize, HP2_SMEM);

    setup_kernel<<<NSTEPS, NTHR>>>(module_ids);
    xform_kernel<<<dim3(32, 26), NTHR>>>(W_in, W_bias, W_f, W1, W2);
    for (int s = 0; s < NSTEPS; s++) {
        step_p1<<<2 * MAXT, NTHR2, P1_SMEM>>>(s, emb, entity_ids, b_in, b_bias);
        step_p2<<<2 * MAXT, NTHR2, P2_SMEM>>>(s, b_f);
    }
    head_p1<<<2 * (BB / TILE), NTHR2, P1_SMEM>>>(b1);
    head_p2<<<BB / TILE, NTHR, HP2_SMEM>>>(b2, out);
}

// round 15
// speedup vs baseline: 1.7039x; 1.0342x over previous
#include <cuda_runtime.h>
#include <cuda_bf16.h>
#include <math.h>
#include <stdint.h>

#define BB 4096
#define EE 128
#define MMOD 8
#define NSTEPS 3
#define HDIM 256
#define CDIM 16
#define TILE 64
#define NTHR 256
#define NTHR2 512
#define MAXT 72

#define S128B 272   // row stride (bytes), K=128 bf16 images
#define S256B 528   // row stride, K=256 images
#define HIMG  33792 // one 64x256 bf16 image (64*528)

// P1 smem: A hi/lo + W hi/lo
#define P1_AH 0
#define P1_AL 17408
#define P1_WH 34816
#define P1_WL 69632
#define P1_SMEM 104448
// P2 smem: H hi/lo + Wf-half hi/lo
#define P2_HH 0
#define P2_HL 33792
#define P2_WH 67584
#define P2_WL 101376
#define P2_SMEM 135168
// head P2 smem
#define HP2_HH 0
#define HP2_HL 33792
#define HP2_WH 67584
#define HP2_WL 76032
#define HP2_SMEM 84480

// ---------------- global scratch ------------------------------------------
__device__ uint32_t g_Xpair[2][BB * 64];            // state: packed bf16 hi/lo
__device__ int g_order[NSTEPS * BB];
__device__ int g_tiles[NSTEPS * MAXT * 3];
__device__ __align__(256) uint8_t g_Himg[2][MAXT * HIMG];   // per-tile H images
__device__ __align__(256) uint8_t g_WinT[2][MMOD * 34816];  // [o=128][e=128]
__device__ __align__(256) uint8_t g_WbiT[2][MMOD * 34816];
__device__ __align__(256) uint8_t g_WfT [2][MMOD * 67584];  // [o=128][f=256]
__device__ __align__(256) uint8_t g_W1T [2][69632];         // [j=256][e=128]
__device__ __align__(256) uint8_t g_W2T [2][8448];          // [c=16][j=256]

// ---------------- helpers ---------------------------------------------------
__device__ __forceinline__ uint32_t sptr(const void* p) {
    return (uint32_t)__cvta_generic_to_shared(p);
}
__device__ __forceinline__ void sts32(uint32_t a, uint32_t v) {
    asm volatile("st.shared.b32 [%0], %1;" :: "r"(a), "r"(v) : "memory");
}
// ---- 1D TMA bulk copy + mbarrier ----
__device__ __forceinline__ void mbar_init(uint32_t mb, uint32_t cnt) {
    asm volatile("mbarrier.init.shared.b64 [%0], %1;" :: "r"(mb), "r"(cnt) : "memory");
}
__device__ __forceinline__ void mbar_expect(uint32_t mb, uint32_t bytes) {
    asm volatile("mbarrier.arrive.expect_tx.shared.b64 _, [%0], %1;" :: "r"(mb), "r"(bytes) : "memory");
}
__device__ __forceinline__ void tma_bulk(uint32_t dst, const void* src, uint32_t bytes, uint32_t mb) {
    asm volatile("cp.async.bulk.shared::cluster.global.mbarrier::complete_tx::bytes [%0], [%1], %2, [%3];"
                 :: "r"(dst), "l"(src), "r"(bytes), "r"(mb) : "memory");
}
__device__ __forceinline__ void mbar_wait(uint32_t mb, uint32_t parity) {
    asm volatile(
        "{\n\t.reg .pred P1;\n\t"
        "WL_%=:\n\t"
        "mbarrier.try_wait.parity.acquire.cta.shared::cta.b64 P1, [%0], %1, 0x989680;\n\t"
        "@P1 bra.uni WD_%=;\n\t"
        "bra.uni WL_%=;\n\t"
        "WD_%=:\n\t}" :: "r"(mb), "r"(parity) : "memory");
}
__device__ __forceinline__ void splitf(float v0, float v1, uint32_t& h, uint32_t& l) {
    __nv_bfloat16 h0 = __float2bfloat16(v0), h1 = __float2bfloat16(v1);
    float r0 = v0 - __bfloat162float(h0), r1 = v1 - __bfloat162float(h1);
    __nv_bfloat16 l0 = __float2bfloat16(r0), l1 = __float2bfloat16(r1);
    h = (uint32_t)__bfloat16_as_ushort(h0) | ((uint32_t)__bfloat16_as_ushort(h1) << 16);
    l = (uint32_t)__bfloat16_as_ushort(l0) | ((uint32_t)__bfloat16_as_ushort(l1) << 16);
}
__device__ __forceinline__ void ldsm4(uint32_t* a, uint32_t addr) {
    asm volatile("ldmatrix.sync.aligned.m8n8.x4.shared.b16 {%0,%1,%2,%3}, [%4];"
                 : "=r"(a[0]), "=r"(a[1]), "=r"(a[2]), "=r"(a[3]) : "r"(addr));
}
__device__ __forceinline__ void ldsm2(uint32_t& b0, uint32_t& b1, uint32_t addr) {
    asm volatile("ldmatrix.sync.aligned.m8n8.x2.shared.b16 {%0,%1}, [%2];"
                 : "=r"(b0), "=r"(b1) : "r"(addr));
}
__device__ __forceinline__ void mma4(float* c, const uint32_t* a, uint32_t b0, uint32_t b1) {
    asm volatile("mma.sync.aligned.m16n8k16.row.col.f32.bf16.bf16.f32 "
                 "{%0,%1,%2,%3},{%4,%5,%6,%7},{%8,%9},{%0,%1,%2,%3};"
                 : "+f"(c[0]), "+f"(c[1]), "+f"(c[2]), "+f"(c[3])
                 : "r"(a[0]), "r"(a[1]), "r"(a[2]), "r"(a[3]), "r"(b0), "r"(b1));
}

// Single-M-stripe (16 rows) fragment-reuse warp GEMM, 3-term hi/lo split.
template<int NT, int KC, int SBA, int SBB>
__device__ __forceinline__ void wgemm1(float* acc,
                                       uint32_t aHI, uint32_t aLO,
                                       uint32_t bHI, uint32_t bLO,
                                       int mbase, int nbase, int lane) {
    const uint32_t aoff = (uint32_t)(mbase + (lane & 15)) * SBA + ((lane >> 4) * 16);
    const uint32_t boff = (uint32_t)(nbase + (lane & 7)) * SBB + (((lane >> 3) & 1) * 16);
    const uint32_t AH = aHI + aoff, AL = aLO + aoff;
    const uint32_t BH = bHI + boff, BL = bLO + boff;
#pragma unroll
    for (int k = 0; k < KC; k++) {
        uint32_t ah[4], al[4];
        ldsm4(ah, AH + k * 32);
        ldsm4(al, AL + k * 32);
#pragma unroll
        for (int nt = 0; nt < NT; nt++) {
            uint32_t bh0, bh1, bl0, bl1;
            ldsm2(bh0, bh1, BH + nt * 8 * SBB + k * 32);
            ldsm2(bl0, bl1, BL + nt * 8 * SBB + k * 32);
            float* c = acc + nt * 4;
            mma4(c, ah, bh0, bh1);
            mma4(c, ah, bl0, bl1);
            mma4(c, al, bh0, bh1);
        }
    }
}
// Two-M-stripe variant for head_p2.
template<int NT, int KS, int SBA, int SBB>
__device__ __forceinline__ void wgemm(float* acc,
                                      uint32_t aHI, uint32_t aLO,
                                      uint32_t bHI, uint32_t bLO,
                                      int mbase, int nbase, int lane) {
    const uint32_t aoff = (uint32_t)(mbase + (lane & 15)) * SBA + ((lane >> 4) * 16);
    const uint32_t boff = (uint32_t)(nbase + (lane & 7)) * SBB + (((lane >> 3) & 1) * 16);
    const uint32_t AH = aHI + aoff, AL = aLO + aoff;
    const uint32_t BH = bHI + boff, BL = bLO + boff;
#pragma unroll
    for (int k = 0; k < KS; k++) {
        uint32_t ah0[4], ah1[4], al0[4], al1[4];
        ldsm4(ah0, AH + k * 32);
        ldsm4(ah1, AH + 16 * SBA + k * 32);
        ldsm4(al0, AL + k * 32);
        ldsm4(al1, AL + 16 * SBA + k * 32);
#pragma unroll
        for (int nt = 0; nt < NT; nt++) {
            uint32_t bh0, bh1, bl0, bl1;
            ldsm2(bh0, bh1, BH + nt * 8 * SBB + k * 32);
            ldsm2(bl0, bl1, BL + nt * 8 * SBB + k * 32);
            float* c0 = acc + (0 * NT + nt) * 4;
            float* c1 = acc + (1 * NT + nt) * 4;
            mma4(c0, ah0, bh0, bh1);
            mma4(c1, ah1, bh0, bh1);
            mma4(c0, ah0, bl0, bl1);
            mma4(c1, ah1, bl0, bl1);
            mma4(c0, al0, bh0, bh1);
            mma4(c1, al1, bh0, bh1);
        }
    }
}

// ---------------------------------------------------------------------------
__global__ void setup_kernel(const int* __restrict__ module_ids) {
    __shared__ int cnt[MMOD], cur[MMOD];
    int tid = threadIdx.x, s = blockIdx.x;
    if (tid < MMOD) cnt[tid] = 0;
    __syncthreads();
    for (int b = tid; b < BB; b += NTHR)
        atomicAdd(&cnt[module_ids[b * NSTEPS + s]], 1);
    __syncthreads();
    if (tid == 0) {
        int o = 0, t = 0;
        for (int m = 0; m < MMOD; m++) {
            cur[m] = o;
            int c = cnt[m];
            for (int ch = 0; ch < c; ch += TILE) {
                g_tiles[(s * MAXT + t) * 3 + 0] = m;
                g_tiles[(s * MAXT + t) * 3 + 1] = o + ch;
                g_tiles[(s * MAXT + t) * 3 + 2] = min(TILE, c - ch);
                t++;
            }
            o += c;
        }
        for (; t < MAXT; t++) g_tiles[(s * MAXT + t) * 3 + 2] = 0;
    }
    __syncthreads();
    for (int b = tid; b < BB; b += NTHR) {
        int m = module_ids[b * NSTEPS + s];
        int p = atomicAdd(&cur[m], 1);
        g_order[s * BB + p] = b;
    }
}

__global__ void xform_kernel(const float* __restrict__ W_in,
                             const float* __restrict__ W_bias,
                             const float* __restrict__ W_f,
                             const float* __restrict__ W1,
                             const float* __restrict__ W2) {
    int j = blockIdx.y;
    const float* src; uint8_t *dh, *dl; int R, C, SB;
    if (j < 8)       { src = W_in + j * 16384;  dh = g_WinT[0] + j * 34816; dl = g_WinT[1] + j * 34816; R = 128; C = 128; SB = S128B; }
    else if (j < 16) { int q = j - 8;  src = W_bias + q * 16384; dh = g_WbiT[0] + q * 34816; dl = g_WbiT[1] + q * 34816; R = 128; C = 128; SB = S128B; }
    else if (j < 24) { int q = j - 16; src = W_f + q * 32768;    dh = g_WfT[0] + q * 67584;  dl = g_WfT[1] + q * 67584;  R = 128; C = 256; SB = S256B; }
    else if (j == 24){ src = W1; dh = g_W1T[0]; dl = g_W1T[1]; R = 256; C = 128; SB = S128B; }
    else             { src = W2; dh = g_W2T[0]; dl = g_W2T[1]; R = 16;  C = 256; SB = S256B; }
    int units = R * C / 2;
    for (int u = blockIdx.x * NTHR + threadIdx.x; u < units; u += gridDim.x * NTHR) {
        int rr = u % R, cc = (u / R) * 2;
        float v0 = src[(size_t)cc * R + rr];
        float v1 = src[(size_t)(cc + 1) * R + rr];
        uint32_t h, l;
        splitf(v0, v1, h, l);
        *(uint32_t*)(dh + (size_t)rr * SB + cc * 2) = h;
        *(uint32_t*)(dl + (size_t)rr * SB + cc * 2) = l;
    }
}

// ---------------------------------------------------------------------------
// Step P1: CTA = (tile, half). 512 thr. W staged by 1D TMA bulk. grid 144.
// ---------------------------------------------------------------------------
__global__ __launch_bounds__(NTHR2)
void step_p1(int s, const float* __restrict__ emb, const int* __restrict__ eids,
             const float* __restrict__ b_in, const float* __restrict__ b_bias) {
    extern __shared__ uint8_t raw[];
    const uint32_t base = sptr(raw);
    __shared__ int srow[TILE];
    __shared__ float sb[EE];
    __shared__ uint64_t mbar;
    int tid = threadIdx.x, wid = tid >> 5, lane = tid & 31;
    int t = blockIdx.x >> 1, h = blockIdx.x & 1;

    int m   = g_tiles[(s * MAXT + t) * 3 + 0];
    int bse = g_tiles[(s * MAXT + t) * 3 + 1];
    int cnt = g_tiles[(s * MAXT + t) * 3 + 2];
    if (cnt == 0) return;

    const uint8_t* WH = (h ? g_WbiT[0] : g_WinT[0]) + m * 34816;
    const uint8_t* WL = (h ? g_WbiT[1] : g_WinT[1]) + m * 34816;
    if (tid == 0) {
        mbar_init(sptr(&mbar), 1);
        mbar_expect(sptr(&mbar), 2 * 34816);
        tma_bulk(base + P1_WH, WH, 34816, sptr(&mbar));
        tma_bulk(base + P1_WL, WL, 34816, sptr(&mbar));
    }
    if (tid < TILE) {
        int row = g_order[s * BB + bse + (tid < cnt ? tid : 0)];
        srow[tid] = h ? eids[row * (NSTEPS + 1) + s + 1]
                      : ((s == 0) ? eids[row * (NSTEPS + 1)] : row);
    }
    if (tid < EE) sb[tid] = h ? b_bias[m * EE + tid] : b_in[m * EE + tid];
    __syncthreads();   // mbar init + srow visible

    const bool frompair = (h == 0 && s > 0);
    for (int i = tid; i < TILE * 64; i += NTHR2) {
        int r = i >> 6, k = i & 63;
        uint32_t hh, ll;
        if (frompair) {
            hh = g_Xpair[0][srow[r] * 64 + k];
            ll = g_Xpair[1][srow[r] * 64 + k];
        } else {
            float2 v = *(const float2*)&emb[(size_t)srow[r] * EE + 2 * k];
            splitf(v.x, v.y, hh, ll);
        }
        sts32(base + P1_AH + r * S128B + k * 4, hh);
        sts32(base + P1_AL + r * S128B + k * 4, ll);
    }
    mbar_wait(sptr(&mbar), 0);
    __syncthreads();   // A-tile stores visible

    const int mh = wid >> 2, nq = wid & 3;
    const int g = lane >> 2, cp = (lane & 3) * 2;
    float acc[4 * 4];
#pragma unroll
    for (int i = 0; i < 16; i++) acc[i] = 0.f;
    wgemm1<4, 8, S128B, S128B>(acc, base + P1_AH, base + P1_AL,
                               base + P1_WH, base + P1_WL, mh * 16, nq * 32, lane);

    uint8_t* HD0 = g_Himg[0] + t * HIMG + h * 256;
    uint8_t* HD1 = g_Himg[1] + t * HIMG + h * 256;
#pragma unroll
    for (int nt = 0; nt < 4; nt++) {
        int r0 = mh * 16 + g;
        int cw = nq * 32 + nt * 8 + cp;
        float* c = acc + nt * 4;
        uint32_t hh, ll;
        splitf(fmaxf(c[0] + sb[cw], 0.f), fmaxf(c[1] + sb[cw + 1], 0.f), hh, ll);
        *(uint32_t*)(HD0 + (size_t)r0 * S256B + cw * 2) = hh;
        *(uint32_t*)(HD1 + (size_t)r0 * S256B + cw * 2) = ll;
        splitf(fmaxf(c[2] + sb[cw], 0.f), fmaxf(c[3] + sb[cw + 1], 0.f), hh, ll);
        *(uint32_t*)(HD0 + (size_t)(r0 + 8) * S256B + cw * 2) = hh;
        *(uint32_t*)(HD1 + (size_t)(r0 + 8) * S256B + cw * 2) = ll;
    }
}

// ---------------------------------------------------------------------------
// Step P2: CTA = (tile, N-half). H + Wf-half staged by TMA bulk. grid 144.
// ---------------------------------------------------------------------------
__global__ __launch_bounds__(NTHR2)
void step_p2(int s, const float* __restrict__ b_f) {
    extern __shared__ uint8_t raw[];
    const uint32_t base = sptr(raw);
    __shared__ int ridx[TILE];
    __shared__ float sb[TILE];
    __shared__ uint64_t mbar;
    int tid = threadIdx.x, wid = tid >> 5, lane = tid & 31;
    int t = blockIdx.x >> 1, nh = blockIdx.x & 1;

    int m   = g_tiles[(s * MAXT + t) * 3 + 0];
    int bse = g_tiles[(s * MAXT + t) * 3 + 1];
    int cnt = g_tiles[(s * MAXT + t) * 3 + 2];
    if (cnt == 0) return;

    if (tid == 0) {
        mbar_init(sptr(&mbar), 1);
        mbar_expect(sptr(&mbar), 4 * 33792);
        tma_bulk(base + P2_HH, g_Himg[0] + t * HIMG, 33792, sptr(&mbar));
        tma_bulk(base + P2_HL, g_Himg[1] + t * HIMG, 33792, sptr(&mbar));
        tma_bulk(base + P2_WH, g_WfT[0] + m * 67584 + nh * 33792, 33792, sptr(&mbar));
        tma_bulk(base + P2_WL, g_WfT[1] + m * 67584 + nh * 33792, 33792, sptr(&mbar));
    }
    if (tid < TILE) {
        ridx[tid] = g_order[s * BB + bse + (tid < cnt ? tid : 0)];
        sb[tid] = b_f[m * EE + nh * 64 + tid];
    }
    __syncthreads();   // mbar init visible
    mbar_wait(sptr(&mbar), 0);

    const int mh = wid >> 2, nq = wid & 3;
    const int g = lane >> 2, cp = (lane & 3) * 2;
    float acc[2 * 4];
#pragma unroll
    for (int i = 0; i < 8; i++) acc[i] = 0.f;
    wgemm1<2, 16, S256B, S256B>(acc, base + P2_HH, base + P2_HL,
                                base + P2_WH, base + P2_WL, mh * 16, nq * 16, lane);

#pragma unroll
    for (int nt = 0; nt < 2; nt++) {
        int r0 = mh * 16 + g;
        int cl = nq * 16 + nt * 8 + cp;
        int cg = nh * 64 + cl;
        float* c = acc + nt * 4;
        uint32_t hh, ll;
        if (r0 < cnt) {
            int gr = ridx[r0];
            splitf(tanhf(c[0] + sb[cl]), tanhf(c[1] + sb[cl + 1]), hh, ll);
            g_Xpair[0][gr * 64 + (cg >> 1)] = hh;
            g_Xpair[1][gr * 64 + (cg >> 1)] = ll;
        }
        if (r0 + 8 < cnt) {
            int gr = ridx[r0 + 8];
            splitf(tanhf(c[2] + sb[cl]), tanhf(c[3] + sb[cl + 1]), hh, ll);
            g_Xpair[0][gr * 64 + (cg >> 1)] = hh;
            g_Xpair[1][gr * 64 + (cg >> 1)] = ll;
        }
    }
}

// ---------------------------------------------------------------------------
// Head P1: CTA = (tile, j-half). W1T half (128 j-rows) by TMA bulk. grid 128.
// ---------------------------------------------------------------------------
__global__ __launch_bounds__(NTHR2)
void head_p1(const float* __restrict__ b1) {
    extern __shared__ uint8_t raw[];
    const uint32_t base = sptr(raw);
    __shared__ float sb[EE];
    __shared__ uint64_t mbar;
    int tid = threadIdx.x, wid = tid >> 5, lane = tid & 31;
    int t = blockIdx.x >> 1, h = blockIdx.x & 1;
    int row0 = t * TILE;

    if (tid == 0) {
        mbar_init(sptr(&mbar), 1);
        mbar_expect(sptr(&mbar), 2 * 34816);
        tma_bulk(base + P1_WH, g_W1T[0] + h * 34816, 34816, sptr(&mbar));
        tma_bulk(base + P1_WL, g_W1T[1] + h * 34816, 34816, sptr(&mbar));
    }
    if (tid < EE) sb[tid] = b1[h * EE + tid];
    __syncthreads();   // mbar init visible

    for (int i = tid; i < TILE * 64; i += NTHR2) {
        int r = i >> 6, k = i & 63;
        sts32(base + P1_AH + r * S128B + k * 4, g_Xpair[0][(row0 + r) * 64 + k]);
        sts32(base + P1_AL + r * S128B + k * 4, g_Xpair[1][(row0 + r) * 64 + k]);
    }
    mbar_wait(sptr(&mbar), 0);
    __syncthreads();

    const int mh = wid >> 2, nq = wid & 3;
    const int g = lane >> 2, cp = (lane & 3) * 2;
    float acc[4 * 4];
#pragma unroll
    for (int i = 0; i < 16; i++) acc[i] = 0.f;
    wgemm1<4, 8, S128B, S128B>(acc, base + P1_AH, base + P1_AL,
                               base + P1_WH, base + P1_WL, mh * 16, nq * 32, lane);

    uint8_t* HD0 = g_Himg[0] + t * HIMG + h * 256;
    uint8_t* HD1 = g_Himg[1] + t * HIMG + h * 256;
#pragma unroll
    for (int nt = 0; nt < 4; nt++) {
        int r0 = mh * 16 + g;
        int cw = nq * 32 + nt * 8 + cp;
        float* c = acc + nt * 4;
        uint32_t hh, ll;
        splitf(fmaxf(c[0] + sb[cw], 0.f), fmaxf(c[1] + sb[cw + 1], 0.f), hh, ll);
        *(uint32_t*)(HD0 + (size_t)r0 * S256B + cw * 2) = hh;
        *(uint32_t*)(HD1 + (size_t)r0 * S256B + cw * 2) = ll;
        splitf(fmaxf(c[2] + sb[cw], 0.f), fmaxf(c[3] + sb[cw + 1], 0.f), hh, ll);
        *(uint32_t*)(HD0 + (size_t)(r0 + 8) * S256B + cw * 2) = hh;
        *(uint32_t*)(HD1 + (size_t)(r0 + 8) * S256B + cw * 2) = ll;
    }
}

// ---------------------------------------------------------------------------
// Head P2: out tile = H @ W2 + b2. TMA bulk staging. grid = 64, 256 thr.
// ---------------------------------------------------------------------------
__global__ __launch_bounds__(NTHR)
void head_p2(const float* __restrict__ b2, float* __restrict__ out) {
    extern __shared__ uint8_t raw[];
    const uint32_t base = sptr(raw);
    __shared__ float sb2[CDIM];
    __shared__ uint64_t mbar;
    int tid = threadIdx.x, wid = tid >> 5, lane = tid & 31;
    int t = blockIdx.x;
    int row0 = t * TILE;

    if (tid == 0) {
        mbar_init(sptr(&mbar), 1);
        mbar_expect(sptr(&mbar), 2 * 33792 + 2 * 8448);
        tma_bulk(base + HP2_HH, g_Himg[0] + t * HIMG, 33792, sptr(&mbar));
        tma_bulk(base + HP2_HL, g_Himg[1] + t * HIMG, 33792, sptr(&mbar));
        tma_bulk(base + HP2_WH, g_W2T[0], 8448, sptr(&mbar));
        tma_bulk(base + HP2_WL, g_W2T[1], 8448, sptr(&mbar));
    }
    if (tid < CDIM) sb2[tid] = b2[tid];
    __syncthreads();   // mbar init visible
    mbar_wait(sptr(&mbar), 0);

    if (wid < 4) {
        const int mh = wid >> 1, nq = wid & 1;
        const int g = lane >> 2, cp = (lane & 3) * 2;
        float acc[2 * 1 * 4];
#pragma unroll
        for (int i = 0; i < 8; i++) acc[i] = 0.f;
        wgemm<1, 16, S256B, S256B>(acc, base + HP2_HH, base + HP2_HL,
                                   base + HP2_WH, base + HP2_WL, mh * 32, nq * 8, lane);
#pragma unroll
        for (int ms = 0; ms < 2; ms++) {
            int r = row0 + mh * 32 + ms * 16 + g;
            int c0 = nq * 8 + cp;
            float* c = acc + ms * 4;
            out[r * CDIM + c0]           = c[0] + sb2[c0];
            out[r * CDIM + c0 + 1]       = c[1] + sb2[c0 + 1];
            out[(r + 8) * CDIM + c0]     = c[2] + sb2[c0];
            out[(r + 8) * CDIM + c0 + 1] = c[3] + sb2[c0 + 1];
        }
    }
}

// ---------------------------------------------------------------------------
extern "C" void kernel_launch(void* const* d_in, const int* in_sizes, int n_in,
                              void* d_out, int out_size) {
    const int*   entity_ids = (const int*)d_in[0];
    const int*   module_ids = (const int*)d_in[1];
    const float* emb        = (const float*)d_in[2];
    const float* W_in       = (const float*)d_in[3];
    const float* b_in       = (const float*)d_in[4];
    const float* W_bias     = (const float*)d_in[5];
    const float* b_bias     = (const float*)d_in[6];
    const float* W_f        = (const float*)d_in[7];
    const float* b_f        = (const float*)d_in[8];
    const float* W1         = (const float*)d_in[9];
    const float* b1         = (const float*)d_in[10];
    const float* W2         = (const float*)d_in[11];
    const float* b2         = (const float*)d_in[12];
    float* out = (float*)d_out;

    cudaFuncSetAttribute(step_p1, cudaFuncAttributeMaxDynamicSharedMemorySize, P1_SMEM);
    cudaFuncSetAttribute(step_p2, cudaFuncAttributeMaxDynamicSharedMemorySize, P2_SMEM);
    cudaFuncSetAttribute(head_p1, cudaFuncAttributeMaxDynamicSharedMemorySize, P1_SMEM);
    cudaFuncSetAttribute(head_p2, cudaFuncAttributeMaxDynamicSharedMemorySize, HP2_SMEM);

    setup_kernel<<<NSTEPS, NTHR>>>(module_ids);
    xform_kernel<<<dim3(32, 26), NTHR>>>(W_in, W_bias, W_f, W1, W2);
    for (int s = 0; s < NSTEPS; s++) {
        step_p1<<<2 * MAXT, NTHR2, P1_SMEM>>>(s, emb, entity_ids, b_in, b_bias);
        step_p2<<<2 * MAXT, NTHR2, P2_SMEM>>>(s, b_f);
    }
    head_p1<<<2 * (BB / TILE), NTHR2, P1_SMEM>>>(b1);
    head_p2<<<BB / TILE, NTHR, HP2_SMEM>>>(b2, out);
}

// round 16
// speedup vs baseline: 1.7552x; 1.0301x over previous
#include <cuda_runtime.h>
#include <cuda_bf16.h>
#include <math.h>
#include <stdint.h>

#define BB 4096
#define EE 128
#define MMOD 8
#define NSTEPS 3
#define HDIM 256
#define CDIM 16
#define TILE 64
#define NTHR 256
#define NTHR2 512
#define MAXT 72

#define S128B 272   // row stride (bytes), K=128 bf16 images
#define S256B 528   // row stride, K=256 images
#define HIMG  33792 // one 64x256 bf16 image (64*528)

// P1 smem: A hi/lo + W hi/lo
#define P1_AH 0
#define P1_AL 17408
#define P1_WH 34816
#define P1_WL 69632
#define P1_SMEM 104448
// P2 smem: H hi/lo + Wf-half hi/lo
#define P2_HH 0
#define P2_HL 33792
#define P2_WH 67584
#define P2_WL 101376
#define P2_SMEM 135168
// head P2 smem
#define HP2_HH 0
#define HP2_HL 33792
#define HP2_WH 67584
#define HP2_WL 76032
#define HP2_SMEM 84480

// ---------------- global scratch ------------------------------------------
__device__ uint32_t g_Xpair[2][BB * 64];            // state: packed bf16 hi/lo
__device__ int g_order[NSTEPS * BB];
__device__ int g_tiles[NSTEPS * MAXT * 3];
__device__ __align__(256) uint8_t g_Himg[2][MAXT * HIMG];   // per-tile H images
__device__ __align__(256) uint8_t g_WinT[2][MMOD * 34816];  // [o=128][e=128]
__device__ __align__(256) uint8_t g_WbiT[2][MMOD * 34816];
__device__ __align__(256) uint8_t g_WfT [2][MMOD * 67584];  // [o=128][f=256]
__device__ __align__(256) uint8_t g_W1T [2][69632];         // [j=256][e=128]
__device__ __align__(256) uint8_t g_W2T [2][8448];          // [c=16][j=256]

// ---------------- helpers ---------------------------------------------------
__device__ __forceinline__ uint32_t sptr(const void* p) {
    return (uint32_t)__cvta_generic_to_shared(p);
}
__device__ __forceinline__ void sts32(uint32_t a, uint32_t v) {
    asm volatile("st.shared.b32 [%0], %1;" :: "r"(a), "r"(v) : "memory");
}
// ---- 1D TMA bulk copy + mbarrier ----
__device__ __forceinline__ void mbar_init(uint32_t mb, uint32_t cnt) {
    asm volatile("mbarrier.init.shared.b64 [%0], %1;" :: "r"(mb), "r"(cnt) : "memory");
}
__device__ __forceinline__ void mbar_expect(uint32_t mb, uint32_t bytes) {
    asm volatile("mbarrier.arrive.expect_tx.shared.b64 _, [%0], %1;" :: "r"(mb), "r"(bytes) : "memory");
}
__device__ __forceinline__ void tma_bulk(uint32_t dst, const void* src, uint32_t bytes, uint32_t mb) {
    asm volatile("cp.async.bulk.shared::cluster.global.mbarrier::complete_tx::bytes [%0], [%1], %2, [%3];"
                 :: "r"(dst), "l"(src), "r"(bytes), "r"(mb) : "memory");
}
__device__ __forceinline__ void mbar_wait(uint32_t mb, uint32_t parity) {
    asm volatile(
        "{\n\t.reg .pred P1;\n\t"
        "WL_%=:\n\t"
        "mbarrier.try_wait.parity.acquire.cta.shared::cta.b64 P1, [%0], %1, 0x989680;\n\t"
        "@P1 bra.uni WD_%=;\n\t"
        "bra.uni WL_%=;\n\t"
        "WD_%=:\n\t}" :: "r"(mb), "r"(parity) : "memory");
}
__device__ __forceinline__ void splitf(float v0, float v1, uint32_t& h, uint32_t& l) {
    __nv_bfloat16 h0 = __float2bfloat16(v0), h1 = __float2bfloat16(v1);
    float r0 = v0 - __bfloat162float(h0), r1 = v1 - __bfloat162float(h1);
    __nv_bfloat16 l0 = __float2bfloat16(r0), l1 = __float2bfloat16(r1);
    h = (uint32_t)__bfloat16_as_ushort(h0) | ((uint32_t)__bfloat16_as_ushort(h1) << 16);
    l = (uint32_t)__bfloat16_as_ushort(l0) | ((uint32_t)__bfloat16_as_ushort(l1) << 16);
}
__device__ __forceinline__ void ldsm4(uint32_t* a, uint32_t addr) {
    asm volatile("ldmatrix.sync.aligned.m8n8.x4.shared.b16 {%0,%1,%2,%3}, [%4];"
                 : "=r"(a[0]), "=r"(a[1]), "=r"(a[2]), "=r"(a[3]) : "r"(addr));
}
__device__ __forceinline__ void ldsm2(uint32_t& b0, uint32_t& b1, uint32_t addr) {
    asm volatile("ldmatrix.sync.aligned.m8n8.x2.shared.b16 {%0,%1}, [%2];"
                 : "=r"(b0), "=r"(b1) : "r"(addr));
}
__device__ __forceinline__ void mma4(float* c, const uint32_t* a, uint32_t b0, uint32_t b1) {
    asm volatile("mma.sync.aligned.m16n8k16.row.col.f32.bf16.bf16.f32 "
                 "{%0,%1,%2,%3},{%4,%5,%6,%7},{%8,%9},{%0,%1,%2,%3};"
                 : "+f"(c[0]), "+f"(c[1]), "+f"(c[2]), "+f"(c[3])
                 : "r"(a[0]), "r"(a[1]), "r"(a[2]), "r"(a[3]), "r"(b0), "r"(b1));
}

// Single-M-stripe (16 rows) fragment-reuse warp GEMM, 3-term hi/lo split.
template<int NT, int KC, int SBA, int SBB>
__device__ __forceinline__ void wgemm1(float* acc,
                                       uint32_t aHI, uint32_t aLO,
                                       uint32_t bHI, uint32_t bLO,
                                       int mbase, int nbase, int lane) {
    const uint32_t aoff = (uint32_t)(mbase + (lane & 15)) * SBA + ((lane >> 4) * 16);
    const uint32_t boff = (uint32_t)(nbase + (lane & 7)) * SBB + (((lane >> 3) & 1) * 16);
    const uint32_t AH = aHI + aoff, AL = aLO + aoff;
    const uint32_t BH = bHI + boff, BL = bLO + boff;
#pragma unroll
    for (int k = 0; k < KC; k++) {
        uint32_t ah[4], al[4];
        ldsm4(ah, AH + k * 32);
        ldsm4(al, AL + k * 32);
#pragma unroll
        for (int nt = 0; nt < NT; nt++) {
            uint32_t bh0, bh1, bl0, bl1;
            ldsm2(bh0, bh1, BH + nt * 8 * SBB + k * 32);
            ldsm2(bl0, bl1, BL + nt * 8 * SBB + k * 32);
            float* c = acc + nt * 4;
            mma4(c, ah, bh0, bh1);
            mma4(c, ah, bl0, bl1);
            mma4(c, al, bh0, bh1);
        }
    }
}
// Two-M-stripe variant for head_p2.
template<int NT, int KS, int SBA, int SBB>
__device__ __forceinline__ void wgemm(float* acc,
                                      uint32_t aHI, uint32_t aLO,
                                      uint32_t bHI, uint32_t bLO,
                                      int mbase, int nbase, int lane) {
    const uint32_t aoff = (uint32_t)(mbase + (lane & 15)) * SBA + ((lane >> 4) * 16);
    const uint32_t boff = (uint32_t)(nbase + (lane & 7)) * SBB + (((lane >> 3) & 1) * 16);
    const uint32_t AH = aHI + aoff, AL = aLO + aoff;
    const uint32_t BH = bHI + boff, BL = bLO + boff;
#pragma unroll
    for (int k = 0; k < KS; k++) {
        uint32_t ah0[4], ah1[4], al0[4], al1[4];
        ldsm4(ah0, AH + k * 32);
        ldsm4(ah1, AH + 16 * SBA + k * 32);
        ldsm4(al0, AL + k * 32);
        ldsm4(al1, AL + 16 * SBA + k * 32);
#pragma unroll
        for (int nt = 0; nt < NT; nt++) {
            uint32_t bh0, bh1, bl0, bl1;
            ldsm2(bh0, bh1, BH + nt * 8 * SBB + k * 32);
            ldsm2(bl0, bl1, BL + nt * 8 * SBB + k * 32);
            float* c0 = acc + (0 * NT + nt) * 4;
            float* c1 = acc + (1 * NT + nt) * 4;
            mma4(c0, ah0, bh0, bh1);
            mma4(c1, ah1, bh0, bh1);
            mma4(c0, ah0, bl0, bl1);
            mma4(c1, ah1, bl0, bl1);
            mma4(c0, al0, bh0, bh1);
            mma4(c1, al1, bh0, bh1);
        }
    }
}

// ---------------------------------------------------------------------------
__global__ void setup_kernel(const int* __restrict__ module_ids) {
    __shared__ int cnt[MMOD], cur[MMOD];
    int tid = threadIdx.x, s = blockIdx.x;
    if (tid < MMOD) cnt[tid] = 0;
    __syncthreads();
    for (int b = tid; b < BB; b += NTHR)
        atomicAdd(&cnt[module_ids[b * NSTEPS + s]], 1);
    __syncthreads();
    if (tid == 0) {
        int o = 0, t = 0;
        for (int m = 0; m < MMOD; m++) {
            cur[m] = o;
            int c = cnt[m];
            for (int ch = 0; ch < c; ch += TILE) {
                g_tiles[(s * MAXT + t) * 3 + 0] = m;
                g_tiles[(s * MAXT + t) * 3 + 1] = o + ch;
                g_tiles[(s * MAXT + t) * 3 + 2] = min(TILE, c - ch);
                t++;
            }
            o += c;
        }
        for (; t < MAXT; t++) g_tiles[(s * MAXT + t) * 3 + 2] = 0;
    }
    __syncthreads();
    for (int b = tid; b < BB; b += NTHR) {
        int m = module_ids[b * NSTEPS + s];
        int p = atomicAdd(&cur[m], 1);
        g_order[s * BB + p] = b;
    }
}

__global__ void xform_kernel(const float* __restrict__ W_in,
                             const float* __restrict__ W_bias,
                             const float* __restrict__ W_f,
                             const float* __restrict__ W1,
                             const float* __restrict__ W2) {
    int j = blockIdx.y;
    const float* src; uint8_t *dh, *dl; int R, C, SB;
    if (j < 8)       { src = W_in + j * 16384;  dh = g_WinT[0] + j * 34816; dl = g_WinT[1] + j * 34816; R = 128; C = 128; SB = S128B; }
    else if (j < 16) { int q = j - 8;  src = W_bias + q * 16384; dh = g_WbiT[0] + q * 34816; dl = g_WbiT[1] + q * 34816; R = 128; C = 128; SB = S128B; }
    else if (j < 24) { int q = j - 16; src = W_f + q * 32768;    dh = g_WfT[0] + q * 67584;  dl = g_WfT[1] + q * 67584;  R = 128; C = 256; SB = S256B; }
    else if (j == 24){ src = W1; dh = g_W1T[0]; dl = g_W1T[1]; R = 256; C = 128; SB = S128B; }
    else             { src = W2; dh = g_W2T[0]; dl = g_W2T[1]; R = 16;  C = 256; SB = S256B; }
    int units = R * C / 2;
    for (int u = blockIdx.x * NTHR + threadIdx.x; u < units; u += gridDim.x * NTHR) {
        int rr = u % R, cc = (u / R) * 2;
        float v0 = src[(size_t)cc * R + rr];
        float v1 = src[(size_t)(cc + 1) * R + rr];
        uint32_t h, l;
        splitf(v0, v1, h, l);
        *(uint32_t*)(dh + (size_t)rr * SB + cc * 2) = h;
        *(uint32_t*)(dl + (size_t)rr * SB + cc * 2) = l;
    }
}

// ---------------------------------------------------------------------------
// Step P1: CTA = (tile, half). 512 thr. W staged via 4 chunked TMA transfers
// (32 o-rows each); warp nq waits only on its chunk. grid 144.
// ---------------------------------------------------------------------------
__global__ __launch_bounds__(NTHR2)
void step_p1(int s, const float* __restrict__ emb, const int* __restrict__ eids,
             const float* __restrict__ b_in, const float* __restrict__ b_bias) {
    extern __shared__ uint8_t raw[];
    const uint32_t base = sptr(raw);
    __shared__ int srow[TILE];
    __shared__ float sb[EE];
    __shared__ __align__(8) uint64_t mbar[4];
    int tid = threadIdx.x, wid = tid >> 5, lane = tid & 31;
    int t = blockIdx.x >> 1, h = blockIdx.x & 1;

    int m   = g_tiles[(s * MAXT + t) * 3 + 0];
    int bse = g_tiles[(s * MAXT + t) * 3 + 1];
    int cnt = g_tiles[(s * MAXT + t) * 3 + 2];
    if (cnt == 0) return;

    const uint8_t* WH = (h ? g_WbiT[0] : g_WinT[0]) + m * 34816;
    const uint8_t* WL = (h ? g_WbiT[1] : g_WinT[1]) + m * 34816;
    if (tid == 0) {
#pragma unroll
        for (int c = 0; c < 4; c++) {
            uint32_t mb = sptr(&mbar[c]);
            mbar_init(mb, 1);
            mbar_expect(mb, 2 * 8704);
            tma_bulk(base + P1_WH + c * 8704, WH + c * 8704, 8704, mb);
            tma_bulk(base + P1_WL + c * 8704, WL + c * 8704, 8704, mb);
        }
    }
    if (tid < TILE) {
        int row = g_order[s * BB + bse + (tid < cnt ? tid : 0)];
        srow[tid] = h ? eids[row * (NSTEPS + 1) + s + 1]
                      : ((s == 0) ? eids[row * (NSTEPS + 1)] : row);
    }
    if (tid < EE) sb[tid] = h ? b_bias[m * EE + tid] : b_in[m * EE + tid];
    __syncthreads();   // mbar init + srow visible

    const bool frompair = (h == 0 && s > 0);
    for (int i = tid; i < TILE * 64; i += NTHR2) {
        int r = i >> 6, k = i & 63;
        uint32_t hh, ll;
        if (frompair) {
            hh = g_Xpair[0][srow[r] * 64 + k];
            ll = g_Xpair[1][srow[r] * 64 + k];
        } else {
            float2 v = *(const float2*)&emb[(size_t)srow[r] * EE + 2 * k];
            splitf(v.x, v.y, hh, ll);
        }
        sts32(base + P1_AH + r * S128B + k * 4, hh);
        sts32(base + P1_AL + r * S128B + k * 4, ll);
    }
    __syncthreads();   // A-tile stores visible

    const int mh = wid >> 2, nq = wid & 3;
    const int g = lane >> 2, cp = (lane & 3) * 2;
    float acc[4 * 4];
#pragma unroll
    for (int i = 0; i < 16; i++) acc[i] = 0.f;
    mbar_wait(sptr(&mbar[nq]), 0);   // only this warp's 32-col W chunk
    wgemm1<4, 8, S128B, S128B>(acc, base + P1_AH, base + P1_AL,
                               base + P1_WH, base + P1_WL, mh * 16, nq * 32, lane);

    uint8_t* HD0 = g_Himg[0] + t * HIMG + h * 256;
    uint8_t* HD1 = g_Himg[1] + t * HIMG + h * 256;
#pragma unroll
    for (int nt = 0; nt < 4; nt++) {
        int r0 = mh * 16 + g;
        int cw = nq * 32 + nt * 8 + cp;
        float* c = acc + nt * 4;
        uint32_t hh, ll;
        splitf(fmaxf(c[0] + sb[cw], 0.f), fmaxf(c[1] + sb[cw + 1], 0.f), hh, ll);
        *(uint32_t*)(HD0 + (size_t)r0 * S256B + cw * 2) = hh;
        *(uint32_t*)(HD1 + (size_t)r0 * S256B + cw * 2) = ll;
        splitf(fmaxf(c[2] + sb[cw], 0.f), fmaxf(c[3] + sb[cw + 1], 0.f), hh, ll);
        *(uint32_t*)(HD0 + (size_t)(r0 + 8) * S256B + cw * 2) = hh;
        *(uint32_t*)(HD1 + (size_t)(r0 + 8) * S256B + cw * 2) = ll;
    }
}

// ---------------------------------------------------------------------------
// Step P2: CTA = (tile, N-half). 4 chunked TMA transfers: mbar[i] carries
// H-stripe i (16 M-rows, hi+lo) + W-stripe i (16 N-rows, hi+lo).
// Warp (mh, nq) waits mbar[mh] and mbar[nq]. grid 144.
// ---------------------------------------------------------------------------
__global__ __launch_bounds__(NTHR2)
void step_p2(int s, const float* __restrict__ b_f) {
    extern __shared__ uint8_t raw[];
    const uint32_t base = sptr(raw);
    __shared__ int ridx[TILE];
    __shared__ float sb[TILE];
    __shared__ __align__(8) uint64_t mbar[4];
    int tid = threadIdx.x, wid = tid >> 5, lane = tid & 31;
    int t = blockIdx.x >> 1, nh = blockIdx.x & 1;

    int m   = g_tiles[(s * MAXT + t) * 3 + 0];
    int bse = g_tiles[(s * MAXT + t) * 3 + 1];
    int cnt = g_tiles[(s * MAXT + t) * 3 + 2];
    if (cnt == 0) return;

    const uint8_t* H0 = g_Himg[0] + t * HIMG;
    const uint8_t* H1 = g_Himg[1] + t * HIMG;
    const uint8_t* W0 = g_WfT[0] + m * 67584 + nh * 33792;
    const uint8_t* W1p = g_WfT[1] + m * 67584 + nh * 33792;
    if (tid == 0) {
#pragma unroll
        for (int c = 0; c < 4; c++) {
            uint32_t mb = sptr(&mbar[c]);
            mbar_init(mb, 1);
            mbar_expect(mb, 4 * 8448);
            tma_bulk(base + P2_HH + c * 8448, H0 + c * 8448, 8448, mb);
            tma_bulk(base + P2_HL + c * 8448, H1 + c * 8448, 8448, mb);
            tma_bulk(base + P2_WH + c * 8448, W0 + c * 8448, 8448, mb);
            tma_bulk(base + P2_WL + c * 8448, W1p + c * 8448, 8448, mb);
        }
    }
    if (tid < TILE) {
        ridx[tid] = g_order[s * BB + bse + (tid < cnt ? tid : 0)];
        sb[tid] = b_f[m * EE + nh * 64 + tid];
    }
    __syncthreads();   // mbar init visible

    const int mh = wid >> 2, nq = wid & 3;
    const int g = lane >> 2, cp = (lane & 3) * 2;
    float acc[2 * 4];
#pragma unroll
    for (int i = 0; i < 8; i++) acc[i] = 0.f;
    mbar_wait(sptr(&mbar[mh]), 0);                 // H stripe for this warp's rows
    if (nq != mh) mbar_wait(sptr(&mbar[nq]), 0);   // W stripe for this warp's cols
    wgemm1<2, 16, S256B, S256B>(acc, base + P2_HH, base + P2_HL,
                                base + P2_WH, base + P2_WL, mh * 16, nq * 16, lane);

#pragma unroll
    for (int nt = 0; nt < 2; nt++) {
        int r0 = mh * 16 + g;
        int cl = nq * 16 + nt * 8 + cp;
        int cg = nh * 64 + cl;
        float* c = acc + nt * 4;
        uint32_t hh, ll;
        if (r0 < cnt) {
            int gr = ridx[r0];
            splitf(tanhf(c[0] + sb[cl]), tanhf(c[1] + sb[cl + 1]), hh, ll);
            g_Xpair[0][gr * 64 + (cg >> 1)] = hh;
            g_Xpair[1][gr * 64 + (cg >> 1)] = ll;
        }
        if (r0 + 8 < cnt) {
            int gr = ridx[r0 + 8];
            splitf(tanhf(c[2] + sb[cl]), tanhf(c[3] + sb[cl + 1]), hh, ll);
            g_Xpair[0][gr * 64 + (cg >> 1)] = hh;
            g_Xpair[1][gr * 64 + (cg >> 1)] = ll;
        }
    }
}

// ---------------------------------------------------------------------------
// Head P1: CTA = (tile, j-half). 4 chunked W transfers (32 j-rows each).
// grid 128.
// ---------------------------------------------------------------------------
__global__ __launch_bounds__(NTHR2)
void head_p1(const float* __restrict__ b1) {
    extern __shared__ uint8_t raw[];
    const uint32_t base = sptr(raw);
    __shared__ float sb[EE];
    __shared__ __align__(8) uint64_t mbar[4];
    int tid = threadIdx.x, wid = tid >> 5, lane = tid & 31;
    int t = blockIdx.x >> 1, h = blockIdx.x & 1;
    int row0 = t * TILE;

    const uint8_t* WH = g_W1T[0] + h * 34816;
    const uint8_t* WL = g_W1T[1] + h * 34816;
    if (tid == 0) {
#pragma unroll
        for (int c = 0; c < 4; c++) {
            uint32_t mb = sptr(&mbar[c]);
            mbar_init(mb, 1);
            mbar_expect(mb, 2 * 8704);
            tma_bulk(base + P1_WH + c * 8704, WH + c * 8704, 8704, mb);
            tma_bulk(base + P1_WL + c * 8704, WL + c * 8704, 8704, mb);
        }
    }
    if (tid < EE) sb[tid] = b1[h * EE + tid];
    __syncthreads();   // mbar init visible

    for (int i = tid; i < TILE * 64; i += NTHR2) {
        int r = i >> 6, k = i & 63;
        sts32(base + P1_AH + r * S128B + k * 4, g_Xpair[0][(row0 + r) * 64 + k]);
        sts32(base + P1_AL + r * S128B + k * 4, g_Xpair[1][(row0 + r) * 64 + k]);
    }
    __syncthreads();

    const int mh = wid >> 2, nq = wid & 3;
    const int g = lane >> 2, cp = (lane & 3) * 2;
    float acc[4 * 4];
#pragma unroll
    for (int i = 0; i < 16; i++) acc[i] = 0.f;
    mbar_wait(sptr(&mbar[nq]), 0);
    wgemm1<4, 8, S128B, S128B>(acc, base + P1_AH, base + P1_AL,
                               base + P1_WH, base + P1_WL, mh * 16, nq * 32, lane);

    uint8_t* HD0 = g_Himg[0] + t * HIMG + h * 256;
    uint8_t* HD1 = g_Himg[1] + t * HIMG + h * 256;
#pragma unroll
    for (int nt = 0; nt < 4; nt++) {
        int r0 = mh * 16 + g;
        int cw = nq * 32 + nt * 8 + cp;
        float* c = acc + nt * 4;
        uint32_t hh, ll;
        splitf(fmaxf(c[0] + sb[cw], 0.f), fmaxf(c[1] + sb[cw + 1], 0.f), hh, ll);
        *(uint32_t*)(HD0 + (size_t)r0 * S256B + cw * 2) = hh;
        *(uint32_t*)(HD1 + (size_t)r0 * S256B + cw * 2) = ll;
        splitf(fmaxf(c[2] + sb[cw], 0.f), fmaxf(c[3] + sb[cw + 1], 0.f), hh, ll);
        *(uint32_t*)(HD0 + (size_t)(r0 + 8) * S256B + cw * 2) = hh;
        *(uint32_t*)(HD1 + (size_t)(r0 + 8) * S256B + cw * 2) = ll;
    }
}

// ---------------------------------------------------------------------------
// Head P2: out tile = H @ W2 + b2. TMA bulk staging. grid = 64, 256 thr.
// ---------------------------------------------------------------------------
__global__ __launch_bounds__(NTHR)
void head_p2(const float* __restrict__ b2, float* __restrict__ out) {
    extern __shared__ uint8_t raw[];
    const uint32_t base = sptr(raw);
    __shared__ float sb2[CDIM];
    __shared__ uint64_t mbar;
    int tid = threadIdx.x, wid = tid >> 5, lane = tid & 31;
    int t = blockIdx.x;
    int row0 = t * TILE;

    if (tid == 0) {
        mbar_init(sptr(&mbar), 1);
        mbar_expect(sptr(&mbar), 2 * 33792 + 2 * 8448);
        tma_bulk(base + HP2_HH, g_Himg[0] + t * HIMG, 33792, sptr(&mbar));
        tma_bulk(base + HP2_HL, g_Himg[1] + t * HIMG, 33792, sptr(&mbar));
        tma_bulk(base + HP2_WH, g_W2T[0], 8448, sptr(&mbar));
        tma_bulk(base + HP2_WL, g_W2T[1], 8448, sptr(&mbar));
    }
    if (tid < CDIM) sb2[tid] = b2[tid];
    __syncthreads();   // mbar init visible
    mbar_wait(sptr(&mbar), 0);

    if (wid < 4) {
        const int mh = wid >> 1, nq = wid & 1;
        const int g = lane >> 2, cp = (lane & 3) * 2;
        float acc[2 * 1 * 4];
#pragma unroll
        for (int i = 0; i < 8; i++) acc[i] = 0.f;
        wgemm<1, 16, S256B, S256B>(acc, base + HP2_HH, base + HP2_HL,
                                   base + HP2_WH, base + HP2_WL, mh * 32, nq * 8, lane);
#pragma unroll
        for (int ms = 0; ms < 2; ms++) {
            int r = row0 + mh * 32 + ms * 16 + g;
            int c0 = nq * 8 + cp;
            float* c = acc + ms * 4;
            out[r * CDIM + c0]           = c[0] + sb2[c0];
            out[r * CDIM + c0 + 1]       = c[1] + sb2[c0 + 1];
            out[(r + 8) * CDIM + c0]     = c[2] + sb2[c0];
            out[(r + 8) * CDIM + c0 + 1] = c[3] + sb2[c0 + 1];
        }
    }
}

// ---------------------------------------------------------------------------
extern "C" void kernel_launch(void* const* d_in, const int* in_sizes, int n_in,
                              void* d_out, int out_size) {
    const int*   entity_ids = (const int*)d_in[0];
    const int*   module_ids = (const int*)d_in[1];
    const float* emb        = (const float*)d_in[2];
    const float* W_in       = (const float*)d_in[3];
    const float* b_in       = (const float*)d_in[4];
    const float* W_bias     = (const float*)d_in[5];
    const float* b_bias     = (const float*)d_in[6];
    const float* W_f        = (const float*)d_in[7];
    const float* b_f        = (const float*)d_in[8];
    const float* W1         = (const float*)d_in[9];
    const float* b1         = (const float*)d_in[10];
    const float* W2         = (const float*)d_in[11];
    const float* b2         = (const float*)d_in[12];
    float* out = (float*)d_out;

    cudaFuncSetAttribute(step_p1, cudaFuncAttributeMaxDynamicSharedMemorySize, P1_SMEM);
    cudaFuncSetAttribute(step_p2, cudaFuncAttributeMaxDynamicSharedMemorySize, P2_SMEM);
    cudaFuncSetAttribute(head_p1, cudaFuncAttributeMaxDynamicSharedMemorySize, P1_SMEM);
    cudaFuncSetAttribute(head_p2, cudaFuncAttributeMaxDynamicSharedMemorySize, HP2_SMEM);

    setup_kernel<<<NSTEPS, NTHR>>>(module_ids);
    xform_kernel<<<dim3(32, 26), NTHR>>>(W_in, W_bias, W_f, W1, W2);
    for (int s = 0; s < NSTEPS; s++) {
        step_p1<<<2 * MAXT, NTHR2, P1_SMEM>>>(s, emb, entity_ids, b_in, b_bias);
        step_p2<<<2 * MAXT, NTHR2, P2_SMEM>>>(s, b_f);
    }
    head_p1<<<2 * (BB / TILE), NTHR2, P1_SMEM>>>(b1);
    head_p2<<<BB / TILE, NTHR, HP2_SMEM>>>(b2, out);
}